// round 14
// baseline (speedup 1.0000x reference)
#include <cuda_runtime.h>
#include <cuda_bf16.h>
#include <math.h>
#include <stdint.h>

#define BB 4
#define TT 1024
#define DD 1024
#define NN 16
#define MM (BB*TT)   // 4096

// GEMM tiling: 128x128 CTA tile, 256 thr, 2 CTA/SM (R8-proven config)
#define Bb16 __nv_bfloat16
#define GBM 128
#define GBN 128
#define GBK 32
#define ROWB 64
#define TILE_T (GBM*ROWB)       // 8192 per digit tile
#define OFF_AH 0
#define OFF_AL (TILE_T)
#define OFF_BH (2*TILE_T)
#define OFF_BL (3*TILE_T)
#define STAGE_B (4*TILE_T)      // 32768
#define NPIPE 3
#define GEMM_SMEM (NPIPE*STAGE_B)   // 98304
#define NSTAGE (DD/GBK)         // 32

// ---------------- scratch ----------------
__device__ __align__(256) float g_x1[MM*DD];
__device__ __align__(256) float g_z [MM*DD];
__device__ __align__(256) float g_x3[MM*DD];
__device__ __align__(256) float g_dt[MM*DD];
__device__ __align__(256) float g_Bm[MM*NN];
__device__ __align__(256) float g_Cm[MM*NN];

__device__ __align__(256) Bb16 g_uh[MM*DD],  g_ul[MM*DD];
__device__ __align__(256) Bb16 g_x3h[MM*DD], g_x3l[MM*DD];
__device__ __align__(256) Bb16 g_yh[MM*DD],  g_yl[MM*DD];
__device__ __align__(256) Bb16 g_Wint_h[DD*DD], g_Wint_l[DD*DD];
__device__ __align__(256) Bb16 g_Wgt_h [DD*DD], g_Wgt_l [DD*DD];
__device__ __align__(256) Bb16 g_Wdtt_h[DD*DD], g_Wdtt_l[DD*DD];
__device__ __align__(256) Bb16 g_Wot_h [DD*DD], g_Wot_l [DD*DD];

__device__ __forceinline__ float silu_f(float v) { return v / (1.f + __expf(-v)); }
__device__ __forceinline__ float softplus_f(float v) { return (v > 20.f) ? v : log1pf(__expf(v)); }

__device__ __forceinline__ uint32_t smem_to_u32(const void* p) {
    uint32_t a;
    asm("{ .reg .u64 t; cvta.to.shared.u64 t, %1; cvt.u32.u64 %0, t; }" : "=r"(a) : "l"(p));
    return a;
}
__device__ __forceinline__ void cpa16(uint32_t s, const void* g) {
    asm volatile("cp.async.cg.shared.global [%0], [%1], 16;\n" :: "r"(s), "l"(g));
}
__device__ __forceinline__ void cp_commit() { asm volatile("cp.async.commit_group;\n" ::: "memory"); }
template<int N> __device__ __forceinline__ void cp_wait() { asm volatile("cp.async.wait_group %0;\n" :: "n"(N) : "memory"); }

__device__ __forceinline__ void ldsm_x4(uint32_t* r, uint32_t addr) {
    asm volatile("ldmatrix.sync.aligned.m8n8.x4.shared.b16 {%0,%1,%2,%3}, [%4];"
        : "=r"(r[0]), "=r"(r[1]), "=r"(r[2]), "=r"(r[3]) : "r"(addr));
}
__device__ __forceinline__ void ldsm_x2(uint32_t* r, uint32_t addr) {
    asm volatile("ldmatrix.sync.aligned.m8n8.x2.shared.b16 {%0,%1}, [%2];"
        : "=r"(r[0]), "=r"(r[1]) : "r"(addr));
}
__device__ __forceinline__ void mma16816(float* c, const uint32_t* a, const uint32_t* b) {
    asm volatile("mma.sync.aligned.m16n8k16.row.col.f32.bf16.bf16.f32 "
        "{%0,%1,%2,%3}, {%4,%5,%6,%7}, {%8,%9}, {%0,%1,%2,%3};"
        : "+f"(c[0]), "+f"(c[1]), "+f"(c[2]), "+f"(c[3])
        : "r"(a[0]), "r"(a[1]), "r"(a[2]), "r"(a[3]), "r"(b[0]), "r"(b[1]));
}

__device__ __forceinline__ void split2(float v, Bb16& h, Bb16& l) {
    h = __float2bfloat16(v);
    l = __float2bfloat16(v - __bfloat162float(h));
}

// ---------------- shared GEMM body (R8 config): computes one 128x128 tile ----------------
// DUAL=0: single weight set (Bh/Bl, bias, C, MODE template). DUAL=1: bn<8 -> set0 (no act, C0),
// bn>=8 -> set1 (silu, C1).
template<int MODE, int DUAL>
__device__ __forceinline__ void gemm_body(
    const Bb16* __restrict__ Ah, const Bb16* __restrict__ Al,
    const Bb16* __restrict__ B0h, const Bb16* __restrict__ B0l,
    const Bb16* __restrict__ B1h, const Bb16* __restrict__ B1l,
    const float* __restrict__ bias0, const float* __restrict__ bias1,
    float* __restrict__ C0, float* __restrict__ C1)
{
    extern __shared__ char smem[];
    const uint32_t sb = smem_to_u32(smem);
    const int tid = threadIdx.x;
    const int lane = tid & 31;
    const int wid = tid >> 5;
    const int wm = wid & 1;          // 2 warps in M
    const int wn = wid >> 1;         // 4 warps in N
    const int bnr = blockIdx.x;
    const int bm = blockIdx.y;

    const bool second = DUAL && (bnr >= 8);
    const int bn = DUAL ? (second ? bnr - 8 : bnr) : bnr;
    const Bb16* Bh = (DUAL && second) ? B1h : B0h;
    const Bb16* Bl = (DUAL && second) ? B1l : B0l;
    const float* bias = (DUAL && second) ? bias1 : bias0;
    float* C = (DUAL && second) ? C1 : C0;

    float acc[4][4][4];
#pragma unroll
    for (int i = 0; i < 4; i++)
#pragma unroll
        for (int j = 0; j < 4; j++)
#pragma unroll
            for (int k = 0; k < 4; k++) acc[i][j][k] = 0.f;

    const int lrow = tid >> 1;
    const int lcp  = (tid & 1) * 2;
    const int lsw  = (lrow >> 1) & 3;
    const uint32_t s_r = (uint32_t)lrow * ROWB;
    const uint32_t sc0 = s_r + (uint32_t)((lcp + 0) ^ lsw) * 16;
    const uint32_t sc1 = s_r + (uint32_t)((lcp + 1) ^ lsw) * 16;

    const Bb16* gAh = Ah + (size_t)(bm * GBM + lrow) * DD + lcp * 8;
    const Bb16* gAl = Al + (size_t)(bm * GBM + lrow) * DD + lcp * 8;
    const Bb16* gBh = Bh + (size_t)(bn * GBN + lrow) * DD + lcp * 8;
    const Bb16* gBl = Bl + (size_t)(bn * GBN + lrow) * DD + lcp * 8;

    auto load_stage = [&](int buf, int s) {
        const uint32_t st = sb + (uint32_t)buf * STAGE_B;
        const size_t k0 = (size_t)s * GBK;
        cpa16(st + OFF_AH + sc0, gAh + k0);
        cpa16(st + OFF_AH + sc1, gAh + k0 + 8);
        cpa16(st + OFF_AL + sc0, gAl + k0);
        cpa16(st + OFF_AL + sc1, gAl + k0 + 8);
        cpa16(st + OFF_BH + sc0, gBh + k0);
        cpa16(st + OFF_BH + sc1, gBh + k0 + 8);
        cpa16(st + OFF_BL + sc0, gBl + k0);
        cpa16(st + OFF_BL + sc1, gBl + k0 + 8);
        cp_commit();
    };

    load_stage(0, 0);
    load_stage(1, 1);

    const int rA = lane & 15, hiA = lane >> 4;
    const int swA = (rA >> 1) & 3;
    const uint32_t a_base = OFF_AH + (uint32_t)(wm * 64 + rA) * ROWB;
    const uint32_t acs0 = (uint32_t)((0 + hiA) ^ swA) * 16;
    const uint32_t acs1 = (uint32_t)((2 + hiA) ^ swA) * 16;

    const int rB = lane & 7, hiB = (lane >> 3) & 1;
    const int swB = (rB >> 1) & 3;
    const uint32_t b_base = OFF_BH + (uint32_t)(wn * 32 + rB) * ROWB;
    const uint32_t bcs0 = (uint32_t)((0 + hiB) ^ swB) * 16;
    const uint32_t bcs1 = (uint32_t)((2 + hiB) ^ swB) * 16;

    for (int s = 0; s < NSTAGE; s++) {
        const int buf = s - (s / NPIPE) * NPIPE;
        if (s < NSTAGE - 1) cp_wait<1>(); else cp_wait<0>();
        __syncthreads();

        const uint32_t st = sb + (uint32_t)buf * STAGE_B;
#pragma unroll
        for (int kc = 0; kc < 2; kc++) {
            const uint32_t ac = kc ? acs1 : acs0;
            const uint32_t bc = kc ? bcs1 : bcs0;
            uint32_t bhf[4][2], blf[4][2];
#pragma unroll
            for (int nt = 0; nt < 4; nt++) {
                uint32_t ad = st + b_base + (uint32_t)nt * (8 * ROWB) + bc;
                ldsm_x2(bhf[nt], ad);
                ldsm_x2(blf[nt], ad + TILE_T);
            }
#pragma unroll
            for (int mtp = 0; mtp < 2; mtp++) {
                uint32_t ahf[2][4], alf[2][4];
#pragma unroll
                for (int i = 0; i < 2; i++) {
                    uint32_t ad = st + a_base + (uint32_t)(mtp * 2 + i) * (16 * ROWB) + ac;
                    ldsm_x4(ahf[i], ad);
                    ldsm_x4(alf[i], ad + TILE_T);
                }
#pragma unroll
                for (int i = 0; i < 2; i++)
#pragma unroll
                    for (int nt = 0; nt < 4; nt++)
                        mma16816(acc[mtp * 2 + i][nt], ahf[i], bhf[nt]);
#pragma unroll
                for (int i = 0; i < 2; i++)
#pragma unroll
                    for (int nt = 0; nt < 4; nt++)
                        mma16816(acc[mtp * 2 + i][nt], ahf[i], blf[nt]);
#pragma unroll
                for (int i = 0; i < 2; i++)
#pragma unroll
                    for (int nt = 0; nt < 4; nt++)
                        mma16816(acc[mtp * 2 + i][nt], alf[i], bhf[nt]);
            }
        }

        if (s + 2 < NSTAGE) {
            int nb = s + 2;
            load_stage(nb - (nb / NPIPE) * NPIPE, nb);
        }
    }

    const int row0 = bm * GBM + wm * 64 + (lane >> 2);
    const int col0 = bn * GBN + wn * 32 + (lane & 3) * 2;
#pragma unroll
    for (int mt = 0; mt < 4; mt++) {
#pragma unroll
        for (int nt = 0; nt < 4; nt++) {
            const int col = col0 + nt * 8;
            float b0 = bias[col], b1 = bias[col + 1];
#pragma unroll
            for (int half = 0; half < 2; half++) {
                const int row = row0 + mt * 16 + half * 8;
                float v0 = acc[mt][nt][half * 2 + 0] + b0;
                float v1 = acc[mt][nt][half * 2 + 1] + b1;
                if (DUAL) {
                    if (second) { v0 = silu_f(v0); v1 = silu_f(v1); }
                } else {
                    if (MODE == 1) { v0 = silu_f(v0); v1 = silu_f(v1); }
                    else if (MODE == 2) { v0 = softplus_f(v0); v1 = softplus_f(v1); }
                }
                float2 w; w.x = v0; w.y = v1;
                *(float2*)(C + (size_t)row * DD + col) = w;
            }
        }
    }
}

template<int MODE>
__global__ __launch_bounds__(256, 2)
void gemm_mma(const Bb16* __restrict__ Ah, const Bb16* __restrict__ Al,
              const Bb16* __restrict__ Bh, const Bb16* __restrict__ Bl,
              const float* __restrict__ bias, float* __restrict__ C)
{
    gemm_body<MODE, 0>(Ah, Al, Bh, Bl, nullptr, nullptr, bias, nullptr, C, nullptr);
}

__global__ __launch_bounds__(256, 2)
void gemm_dual(const Bb16* __restrict__ Ah, const Bb16* __restrict__ Al,
               const Bb16* __restrict__ B0h, const Bb16* __restrict__ B0l,
               const Bb16* __restrict__ B1h, const Bb16* __restrict__ B1l,
               const float* __restrict__ bias0, const float* __restrict__ bias1,
               float* __restrict__ C0, float* __restrict__ C1)
{
    gemm_body<0, 1>(Ah, Al, B0h, B0l, B1h, B1l, bias0, bias1, C0, C1);
}

// ---------------- elementwise split ----------------
__global__ __launch_bounds__(256)
void split_kernel(const float* __restrict__ X, Bb16* __restrict__ H,
                  Bb16* __restrict__ L, int n4)
{
    for (int i = blockIdx.x * blockDim.x + threadIdx.x; i < n4; i += gridDim.x * blockDim.x) {
        float4 v = ((const float4*)X)[i];
        Bb16 h0, l0, h1, l1, h2, l2, h3, l3;
        split2(v.x, h0, l0); split2(v.y, h1, l1); split2(v.z, h2, l2); split2(v.w, h3, l3);
        __nv_bfloat162 hh0; hh0.x = h0; hh0.y = h1;
        __nv_bfloat162 hh1; hh1.x = h2; hh1.y = h3;
        __nv_bfloat162 ll0; ll0.x = l0; ll0.y = l1;
        __nv_bfloat162 ll1; ll1.x = l2; ll1.y = l3;
        ((__nv_bfloat162*)H)[i * 2]     = hh0;
        ((__nv_bfloat162*)H)[i * 2 + 1] = hh1;
        ((__nv_bfloat162*)L)[i * 2]     = ll0;
        ((__nv_bfloat162*)L)[i * 2 + 1] = ll1;
    }
}

// ---------------- fused transpose+split of all 4 weights ----------------
__global__ __launch_bounds__(256)
void tsplit4_kernel(const float* __restrict__ W0, const float* __restrict__ W1,
                    const float* __restrict__ W2, const float* __restrict__ W3,
                    Bb16* __restrict__ T0h, Bb16* __restrict__ T0l,
                    Bb16* __restrict__ T1h, Bb16* __restrict__ T1l,
                    Bb16* __restrict__ T2h, Bb16* __restrict__ T2l,
                    Bb16* __restrict__ T3h, Bb16* __restrict__ T3l)
{
    __shared__ float s[32][33];
    const int wi = blockIdx.z;
    const float* W = (wi == 0) ? W0 : (wi == 1) ? W1 : (wi == 2) ? W2 : W3;
    Bb16* Th = (wi == 0) ? T0h : (wi == 1) ? T1h : (wi == 2) ? T2h : T3h;
    Bb16* Tl = (wi == 0) ? T0l : (wi == 1) ? T1l : (wi == 2) ? T2l : T3l;
    const int bx = blockIdx.x * 32, by = blockIdx.y * 32;
    const int tx = threadIdx.x, ty = threadIdx.y;
#pragma unroll
    for (int j = ty; j < 32; j += 8)
        s[j][tx] = W[(size_t)(by + j) * DD + bx + tx];
    __syncthreads();
#pragma unroll
    for (int j = ty; j < 32; j += 8) {
        float v = s[tx][j];
        Bb16 h, l;
        split2(v, h, l);
        Th[(size_t)(bx + j) * DD + by + tx] = h;
        Tl[(size_t)(bx + j) * DD + by + tx] = l;
    }
}

// ---------------- depthwise conv3 + silu (+ bf16 split out) ----------------
__global__ __launch_bounds__(256)
void conv_silu_kernel(const float* __restrict__ x1, const float* __restrict__ w,
                      const float* __restrict__ cb, float* __restrict__ x3,
                      Bb16* __restrict__ x3h, Bb16* __restrict__ x3l)
{
    const int total2 = BB * TT * DD / 2;
    for (int i2 = blockIdx.x * blockDim.x + threadIdx.x; i2 < total2; i2 += gridDim.x * blockDim.x) {
        int idx = i2 * 2;
        int d = idx & (DD - 1);
        int t = (idx / DD) & (TT - 1);
        float2 xc = *(const float2*)(x1 + idx);
        float c0 = xc.x * w[d * 3 + 1] + cb[d];
        float c1 = xc.y * w[(d + 1) * 3 + 1] + cb[d + 1];
        if (t > 0) {
            float2 xm = *(const float2*)(x1 + idx - DD);
            c0 = fmaf(xm.x, w[d * 3], c0);
            c1 = fmaf(xm.y, w[(d + 1) * 3], c1);
        }
        if (t < TT - 1) {
            float2 xp = *(const float2*)(x1 + idx + DD);
            c0 = fmaf(xp.x, w[d * 3 + 2], c0);
            c1 = fmaf(xp.y, w[(d + 1) * 3 + 2], c1);
        }
        float2 r; r.x = silu_f(c0); r.y = silu_f(c1);
        *(float2*)(x3 + idx) = r;
        Bb16 h0, l0, h1, l1;
        split2(r.x, h0, l0); split2(r.y, h1, l1);
        __nv_bfloat162 hh; hh.x = h0; hh.y = h1;
        __nv_bfloat162 ll; ll.x = l0; ll.y = l1;
        *(__nv_bfloat162*)(x3h + idx) = hh;
        *(__nv_bfloat162*)(x3l + idx) = ll;
    }
}

// ---------------- B/C projections ----------------
__global__ __launch_bounds__(256)
void proj_bc_kernel(const float* __restrict__ X,
                    const float* __restrict__ Wb, const float* __restrict__ Wc,
                    const float* __restrict__ bb, const float* __restrict__ bc,
                    float* __restrict__ Bm, float* __restrict__ Cm)
{
    __shared__ float Xs[32][33];
    __shared__ float Ws[32][32];
    const int tid = threadIdx.x;
    const int row0 = blockIdx.x * 32;
    const int c = tid & 31;
    const int rq = tid >> 5;
    float acc[4] = {0.f, 0.f, 0.f, 0.f};
    const int lr = tid / 8;
    const int lc = (tid % 8) * 4;

    for (int k0 = 0; k0 < DD; k0 += 32) {
        float4 xv = *(const float4*)(X + (size_t)(row0 + lr) * DD + k0 + lc);
        Xs[lr][lc + 0] = xv.x; Xs[lr][lc + 1] = xv.y;
        Xs[lr][lc + 2] = xv.z; Xs[lr][lc + 3] = xv.w;
#pragma unroll
        for (int q = 0; q < 4; q++) {
            int cc = lc + q;
            float wv = (cc < 16) ? Wb[(size_t)(k0 + lr) * 16 + cc]
                                 : Wc[(size_t)(k0 + lr) * 16 + cc - 16];
            Ws[lr][cc] = wv;
        }
        __syncthreads();
#pragma unroll
        for (int kk = 0; kk < 32; kk++) {
            float w = Ws[kk][c];
#pragma unroll
            for (int r = 0; r < 4; r++)
                acc[r] = fmaf(Xs[rq * 4 + r][kk], w, acc[r]);
        }
        __syncthreads();
    }
#pragma unroll
    for (int r = 0; r < 4; r++) {
        int row = row0 + rq * 4 + r;
        if (c < 16) Bm[(size_t)row * 16 + c]      = acc[r] + bb[c];
        else        Cm[(size_t)row * 16 + c - 16] = acc[r] + bc[c - 16];
    }
}

// ---------------- selective scan: 512 thr, SC=32, cp.async double-buffer ----------------
#define SC 32
__global__ __launch_bounds__(512)
void scan_kernel(const float* __restrict__ dt, const float* __restrict__ x,
                 const float* __restrict__ Bm, const float* __restrict__ Cm,
                 const float* __restrict__ A,  const float* __restrict__ z,
                 Bb16* __restrict__ yh, Bb16* __restrict__ yl)
{
    __shared__ float s_dt[2][SC][32], s_x[2][SC][32], s_z[2][SC][32];
    __shared__ float s_B[2][SC][16], s_C[2][SC][16];
    __shared__ float s_y[SC][32];

    const int blk = blockIdx.x;
    const int b = blk >> 5;
    const int d0 = (blk & 31) * 32;
    const int tid = threadIdx.x;
    const int n = tid & 15;
    const int dl = tid >> 4;
    const int d = d0 + dl;

    const float a = A[(size_t)d * NN + n];
    float h = 0.f;

    const size_t base = (size_t)b * TT * DD;

    const int larr = tid >> 7;
    const int lrw  = (tid & 127) >> 2;
    const int lcc  = tid & 3;
    const int t2   = tid - 384;
    const int barr = t2 >> 6;
    const int brw  = (t2 & 63) >> 1;
    const int bcc  = (t2 & 1) * 2;

    auto load_chunk = [&](int buf, int t0) {
        if (larr < 3) {
            const float* src = (larr == 0) ? dt : (larr == 1) ? x : z;
            float* sdst = (larr == 0) ? &s_dt[buf][lrw][0] :
                          (larr == 1) ? &s_x[buf][lrw][0] : &s_z[buf][lrw][0];
            const float* gsrc = src + base + (size_t)(t0 + lrw) * DD + d0;
            cpa16(smem_to_u32(sdst + lcc * 4),       gsrc + lcc * 4);
            cpa16(smem_to_u32(sdst + (lcc + 4) * 4), gsrc + (lcc + 4) * 4);
        } else {
            const float* src = barr ? Cm : Bm;
            float* sdst = barr ? &s_C[buf][brw][0] : &s_B[buf][brw][0];
            const float* gsrc = src + ((size_t)(b * TT) + t0 + brw) * NN;
            cpa16(smem_to_u32(sdst + bcc * 4),       gsrc + bcc * 4);
            cpa16(smem_to_u32(sdst + (bcc + 1) * 4), gsrc + (bcc + 1) * 4);
        }
        cp_commit();
    };

    load_chunk(0, 0);
    load_chunk(1, SC);

    const int yi = tid >> 5;
    const int yd = tid & 31;

    for (int c = 0; c < TT / SC; c++) {
        const int buf = c & 1;
        const int t0 = c * SC;
        if (c < TT / SC - 1) cp_wait<1>(); else cp_wait<0>();
        __syncthreads();

#pragma unroll 16
        for (int i = 0; i < SC; i++) {
            float dtv = s_dt[buf][i][dl];
            float xv  = s_x[buf][i][dl];
            float Bv  = s_B[buf][i][n];
            float Cv  = s_C[buf][i][n];
            float da  = __expf(dtv * a);
            h = fmaf(da, h, dtv * Bv * xv);
            float p = h * Cv;
            p += __shfl_xor_sync(0xffffffffu, p, 1);
            p += __shfl_xor_sync(0xffffffffu, p, 2);
            p += __shfl_xor_sync(0xffffffffu, p, 4);
            p += __shfl_xor_sync(0xffffffffu, p, 8);
            if (n == 0) s_y[i][dl] = p * s_z[buf][i][dl];
        }
        __syncthreads();

#pragma unroll
        for (int r = 0; r < 2; r++) {
            const int row = yi + r * 16;
            float v = s_y[row][yd];
            Bb16 hh, ll;
            split2(v, hh, ll);
            size_t off = base + (size_t)(t0 + row) * DD + d0 + yd;
            yh[off] = hh;
            yl[off] = ll;
        }

        if (c + 2 < TT / SC) load_chunk(buf, t0 + 2 * SC);
        else cp_commit();
        __syncthreads();
    }
}

// ---------------- launch ----------------
extern "C" void kernel_launch(void* const* d_in, const int* in_sizes, int n_in,
                              void* d_out, int out_size)
{
    const float* u    = (const float*)d_in[0];
    const float* Win  = (const float*)d_in[1];
    const float* b_in = (const float*)d_in[2];
    const float* Wg   = (const float*)d_in[3];
    const float* bg   = (const float*)d_in[4];
    const float* Wout = (const float*)d_in[5];
    const float* bout = (const float*)d_in[6];
    const float* convw= (const float*)d_in[7];
    const float* convb= (const float*)d_in[8];
    const float* A    = (const float*)d_in[9];
    const float* Wb   = (const float*)d_in[10];
    const float* bb   = (const float*)d_in[11];
    const float* Wc   = (const float*)d_in[12];
    const float* bc   = (const float*)d_in[13];
    const float* Wdt  = (const float*)d_in[14];
    const float* bdt  = (const float*)d_in[15];
    float* out = (float*)d_out;

    float *x1, *zb, *x3, *dtb, *Bmb, *Cmb;
    cudaGetSymbolAddress((void**)&x1,  g_x1);
    cudaGetSymbolAddress((void**)&zb,  g_z);
    cudaGetSymbolAddress((void**)&x3,  g_x3);
    cudaGetSymbolAddress((void**)&dtb, g_dt);
    cudaGetSymbolAddress((void**)&Bmb, g_Bm);
    cudaGetSymbolAddress((void**)&Cmb, g_Cm);

    Bb16 *uh, *ul, *x3h, *x3l, *yh, *yl;
    Bb16 *Wint_h, *Wint_l, *Wgt_h, *Wgt_l, *Wdtt_h, *Wdtt_l, *Wot_h, *Wot_l;
    cudaGetSymbolAddress((void**)&uh,  g_uh);   cudaGetSymbolAddress((void**)&ul,  g_ul);
    cudaGetSymbolAddress((void**)&x3h, g_x3h);  cudaGetSymbolAddress((void**)&x3l, g_x3l);
    cudaGetSymbolAddress((void**)&yh,  g_yh);   cudaGetSymbolAddress((void**)&yl,  g_yl);
    cudaGetSymbolAddress((void**)&Wint_h, g_Wint_h); cudaGetSymbolAddress((void**)&Wint_l, g_Wint_l);
    cudaGetSymbolAddress((void**)&Wgt_h,  g_Wgt_h);  cudaGetSymbolAddress((void**)&Wgt_l,  g_Wgt_l);
    cudaGetSymbolAddress((void**)&Wdtt_h, g_Wdtt_h); cudaGetSymbolAddress((void**)&Wdtt_l, g_Wdtt_l);
    cudaGetSymbolAddress((void**)&Wot_h,  g_Wot_h);  cudaGetSymbolAddress((void**)&Wot_l,  g_Wot_l);

    cudaFuncSetAttribute((const void*)gemm_mma<0>, cudaFuncAttributeMaxDynamicSharedMemorySize, GEMM_SMEM);
    cudaFuncSetAttribute((const void*)gemm_mma<2>, cudaFuncAttributeMaxDynamicSharedMemorySize, GEMM_SMEM);
    cudaFuncSetAttribute((const void*)gemm_dual,   cudaFuncAttributeMaxDynamicSharedMemorySize, GEMM_SMEM);

    static cudaStream_t s1 = nullptr;
    static cudaEvent_t ev0 = nullptr, evC = nullptr, evP = nullptr, evU = nullptr;
    if (!s1) {
        int prLo = 0, prHi = 0;
        cudaDeviceGetStreamPriorityRange(&prLo, &prHi);
        cudaStreamCreateWithPriority(&s1, cudaStreamNonBlocking, prLo);
        cudaEventCreateWithFlags(&ev0, cudaEventDisableTiming);
        cudaEventCreateWithFlags(&evC, cudaEventDisableTiming);
        cudaEventCreateWithFlags(&evP, cudaEventDisableTiming);
        cudaEventCreateWithFlags(&evU, cudaEventDisableTiming);
    }
    cudaStream_t s0 = 0;

    dim3 ggd(16, MM / GBM);   // dual: (16, 32) = 512 CTAs
    dim3 gg (8,  MM / GBM);   // single: (8, 32) = 256 CTAs

    cudaEventRecord(ev0, s0);
    cudaStreamWaitEvent(s1, ev0, 0);
    split_kernel<<<2048, 256, 0, s1>>>(u, uh, ul, MM * DD / 4);
    cudaEventRecord(evU, s1);

    tsplit4_kernel<<<dim3(32, 32, 4), dim3(32, 8), 0, s0>>>(Win, Wg, Wdt, Wout,
        Wint_h, Wint_l, Wgt_h, Wgt_l, Wdtt_h, Wdtt_l, Wot_h, Wot_l);
    cudaStreamWaitEvent(s0, evU, 0);

    // merged in_proj + gate (one launch, 512 CTAs)
    gemm_dual<<<ggd, 256, GEMM_SMEM, s0>>>(uh, ul, Wint_h, Wint_l, Wgt_h, Wgt_l,
                                           b_in, bg, x1, zb);

    conv_silu_kernel<<<2048, 256, 0, s0>>>(x1, convw, convb, x3, x3h, x3l);
    cudaEventRecord(evC, s0);

    cudaStreamWaitEvent(s1, evC, 0);
    proj_bc_kernel<<<MM / 32, 256, 0, s1>>>(x3, Wb, Wc, bb, bc, Bmb, Cmb);
    cudaEventRecord(evP, s1);

    gemm_mma<2><<<gg, 256, GEMM_SMEM, s0>>>(x3h, x3l, Wdtt_h, Wdtt_l, bdt, dtb);

    cudaStreamWaitEvent(s0, evP, 0);
    scan_kernel<<<BB * (DD / 32), 512, 0, s0>>>(dtb, x3, Bmb, Cmb, A, zb, yh, yl);
    gemm_mma<0><<<gg, 256, GEMM_SMEM, s0>>>(yh, yl, Wot_h, Wot_l, bout, out);
}

// round 15
// speedup vs baseline: 1.0629x; 1.0629x over previous
#include <cuda_runtime.h>
#include <cuda_bf16.h>
#include <math.h>
#include <stdint.h>

#define BB 4
#define TT 1024
#define DD 1024
#define NN 16
#define MM (BB*TT)   // 4096

// GEMM tiling: 256x128 CTA tile, 512 threads, GBK=32 (R11/R13 proven)
#define Bb16 __nv_bfloat16
#define GBM 256
#define GBN 128
#define GBK 32
#define ROWB 64
#define TILE_A (GBM*ROWB)       // 16384 per digit
#define TILE_Bt (GBN*ROWB)      // 8192 per digit
#define OFF_AH 0
#define OFF_AL (TILE_A)
#define OFF_BH (2*TILE_A)
#define OFF_BL (2*TILE_A + TILE_Bt)
#define STAGE_B (2*TILE_A + 2*TILE_Bt)  // 49152
#define NPIPE 3
#define GEMM_SMEM (NPIPE*STAGE_B)       // 147456
#define NSTAGE (DD/GBK)         // 32

// ---------------- scratch ----------------
__device__ __align__(256) float g_x1[MM*DD];
__device__ __align__(256) float g_z [MM*DD];
__device__ __align__(256) float g_x3[MM*DD];
__device__ __align__(256) float g_dt[MM*DD];
__device__ __align__(256) float g_Bm[MM*NN];
__device__ __align__(256) float g_Cm[MM*NN];

__device__ __align__(256) Bb16 g_uh[MM*DD],  g_ul[MM*DD];
__device__ __align__(256) Bb16 g_x3h[MM*DD], g_x3l[MM*DD];
__device__ __align__(256) Bb16 g_yh[MM*DD],  g_yl[MM*DD];
__device__ __align__(256) Bb16 g_Wint_h[DD*DD], g_Wint_l[DD*DD];
__device__ __align__(256) Bb16 g_Wgt_h [DD*DD], g_Wgt_l [DD*DD];
__device__ __align__(256) Bb16 g_Wdtt_h[DD*DD], g_Wdtt_l[DD*DD];
__device__ __align__(256) Bb16 g_Wot_h [DD*DD], g_Wot_l [DD*DD];

__device__ __forceinline__ float silu_f(float v) { return v / (1.f + __expf(-v)); }
__device__ __forceinline__ float softplus_f(float v) { return (v > 20.f) ? v : log1pf(__expf(v)); }

__device__ __forceinline__ uint32_t smem_to_u32(const void* p) {
    uint32_t a;
    asm("{ .reg .u64 t; cvta.to.shared.u64 t, %1; cvt.u32.u64 %0, t; }" : "=r"(a) : "l"(p));
    return a;
}
__device__ __forceinline__ void cpa16(uint32_t s, const void* g) {
    asm volatile("cp.async.cg.shared.global [%0], [%1], 16;\n" :: "r"(s), "l"(g));
}
__device__ __forceinline__ void cp_commit() { asm volatile("cp.async.commit_group;\n" ::: "memory"); }
template<int N> __device__ __forceinline__ void cp_wait() { asm volatile("cp.async.wait_group %0;\n" :: "n"(N) : "memory"); }

__device__ __forceinline__ void ldsm_x4(uint32_t* r, uint32_t addr) {
    asm volatile("ldmatrix.sync.aligned.m8n8.x4.shared.b16 {%0,%1,%2,%3}, [%4];"
        : "=r"(r[0]), "=r"(r[1]), "=r"(r[2]), "=r"(r[3]) : "r"(addr));
}
__device__ __forceinline__ void ldsm_x2(uint32_t* r, uint32_t addr) {
    asm volatile("ldmatrix.sync.aligned.m8n8.x2.shared.b16 {%0,%1}, [%2];"
        : "=r"(r[0]), "=r"(r[1]) : "r"(addr));
}
__device__ __forceinline__ void mma16816(float* c, const uint32_t* a, const uint32_t* b) {
    asm volatile("mma.sync.aligned.m16n8k16.row.col.f32.bf16.bf16.f32 "
        "{%0,%1,%2,%3}, {%4,%5,%6,%7}, {%8,%9}, {%0,%1,%2,%3};"
        : "+f"(c[0]), "+f"(c[1]), "+f"(c[2]), "+f"(c[3])
        : "r"(a[0]), "r"(a[1]), "r"(a[2]), "r"(a[3]), "r"(b[0]), "r"(b[1]));
}

__device__ __forceinline__ void split2(float v, Bb16& h, Bb16& l) {
    h = __float2bfloat16(v);
    l = __float2bfloat16(v - __bfloat162float(h));
}

// ---------------- shared GEMM body: one 256x128 tile ----------------
// DUAL=1: blockIdx.x in [0,16): <8 -> set0 (no act), >=8 -> set1 (silu)
template<int MODE, int DUAL>
__device__ __forceinline__ void gemm_body(
    const Bb16* __restrict__ Ah, const Bb16* __restrict__ Al,
    const Bb16* __restrict__ B0h, const Bb16* __restrict__ B0l,
    const Bb16* __restrict__ B1h, const Bb16* __restrict__ B1l,
    const float* __restrict__ bias0, const float* __restrict__ bias1,
    float* __restrict__ C0, float* __restrict__ C1)
{
    extern __shared__ char smem[];
    const uint32_t sb = smem_to_u32(smem);
    const int tid = threadIdx.x;
    const int lane = tid & 31;
    const int wid = tid >> 5;
    const int wm = wid & 3;
    const int wn = wid >> 2;
    const int bnr = blockIdx.x;
    const int bm = blockIdx.y;

    const bool second = DUAL && (bnr >= 8);
    const int bn = DUAL ? (second ? bnr - 8 : bnr) : bnr;
    const Bb16* Bh = (DUAL && second) ? B1h : B0h;
    const Bb16* Bl = (DUAL && second) ? B1l : B0l;
    const float* bias = (DUAL && second) ? bias1 : bias0;
    float* C = (DUAL && second) ? C1 : C0;

    float acc[4][4][4];
#pragma unroll
    for (int i = 0; i < 4; i++)
#pragma unroll
        for (int j = 0; j < 4; j++)
#pragma unroll
            for (int k = 0; k < 4; k++) acc[i][j][k] = 0.f;

    const int arow = tid >> 1;
    const int ach  = tid & 1;
    const int asw  = (arow >> 1) & 3;
    const uint32_t a_sc0 = (uint32_t)arow * ROWB + (uint32_t)((ach * 2 + 0) ^ asw) * 16;
    const uint32_t a_sc1 = (uint32_t)arow * ROWB + (uint32_t)((ach * 2 + 1) ^ asw) * 16;
    const Bb16* gAh = Ah + (size_t)(bm * GBM + arow) * DD + ach * 16;
    const Bb16* gAl = Al + (size_t)(bm * GBM + arow) * DD + ach * 16;

    const int brow = (tid & 255) >> 1;
    const int bch  = tid & 1;
    const int bsw  = (brow >> 1) & 3;
    const uint32_t b_sc0 = (uint32_t)brow * ROWB + (uint32_t)((bch * 2 + 0) ^ bsw) * 16;
    const uint32_t b_sc1 = (uint32_t)brow * ROWB + (uint32_t)((bch * 2 + 1) ^ bsw) * 16;
    const Bb16* gBh = Bh + (size_t)(bn * GBN + brow) * DD + bch * 16;
    const Bb16* gBl = Bl + (size_t)(bn * GBN + brow) * DD + bch * 16;
    const bool doB = (tid < 256);

    auto load_stage = [&](int buf, int s) {
        const uint32_t st = sb + (uint32_t)buf * STAGE_B;
        const size_t k0 = (size_t)s * GBK;
        cpa16(st + OFF_AH + a_sc0, gAh + k0);
        cpa16(st + OFF_AH + a_sc1, gAh + k0 + 8);
        cpa16(st + OFF_AL + a_sc0, gAl + k0);
        cpa16(st + OFF_AL + a_sc1, gAl + k0 + 8);
        if (doB) {
            cpa16(st + OFF_BH + b_sc0, gBh + k0);
            cpa16(st + OFF_BH + b_sc1, gBh + k0 + 8);
            cpa16(st + OFF_BL + b_sc0, gBl + k0);
            cpa16(st + OFF_BL + b_sc1, gBl + k0 + 8);
        }
        cp_commit();
    };

    load_stage(0, 0);
    load_stage(1, 1);

    const int rA = lane & 15, hiA = lane >> 4;
    const int swA = (rA >> 1) & 3;
    const uint32_t a_base = OFF_AH + (uint32_t)(wm * 64 + rA) * ROWB;
    const uint32_t acs0 = (uint32_t)((0 + hiA) ^ swA) * 16;
    const uint32_t acs1 = (uint32_t)((2 + hiA) ^ swA) * 16;

    const int rB = lane & 7, hiB = (lane >> 3) & 1;
    const int swB = (rB >> 1) & 3;
    const uint32_t b_base = OFF_BH + (uint32_t)(wn * 32 + rB) * ROWB;
    const uint32_t bcs0 = (uint32_t)((0 + hiB) ^ swB) * 16;
    const uint32_t bcs1 = (uint32_t)((2 + hiB) ^ swB) * 16;

    for (int s = 0; s < NSTAGE; s++) {
        const int buf = s - (s / NPIPE) * NPIPE;
        if (s < NSTAGE - 1) cp_wait<1>(); else cp_wait<0>();
        __syncthreads();

        const uint32_t st = sb + (uint32_t)buf * STAGE_B;
#pragma unroll
        for (int kc = 0; kc < 2; kc++) {
            const uint32_t ac = kc ? acs1 : acs0;
            const uint32_t bc = kc ? bcs1 : bcs0;
            uint32_t bhf[4][2], blf[4][2];
#pragma unroll
            for (int nt = 0; nt < 4; nt++) {
                uint32_t ad = st + b_base + (uint32_t)nt * (8 * ROWB) + bc;
                ldsm_x2(bhf[nt], ad);
                ldsm_x2(blf[nt], ad + TILE_Bt);
            }
#pragma unroll
            for (int mt = 0; mt < 4; mt++) {
                uint32_t ad = st + a_base + (uint32_t)mt * (16 * ROWB) + ac;
                uint32_t ahf[4], alf[4];
                ldsm_x4(ahf, ad);
                ldsm_x4(alf, ad + TILE_A);
#pragma unroll
                for (int nt = 0; nt < 4; nt++) mma16816(acc[mt][nt], ahf, bhf[nt]);
#pragma unroll
                for (int nt = 0; nt < 4; nt++) mma16816(acc[mt][nt], ahf, blf[nt]);
#pragma unroll
                for (int nt = 0; nt < 4; nt++) mma16816(acc[mt][nt], alf, bhf[nt]);
            }
        }

        if (s + 2 < NSTAGE) {
            int nb = s + 2;
            load_stage(nb - (nb / NPIPE) * NPIPE, nb);
        }
    }

    const int row0 = bm * GBM + wm * 64 + (lane >> 2);
    const int col0 = bn * GBN + wn * 32 + (lane & 3) * 2;
#pragma unroll
    for (int mt = 0; mt < 4; mt++) {
#pragma unroll
        for (int nt = 0; nt < 4; nt++) {
            const int col = col0 + nt * 8;
            float b0 = bias[col], b1 = bias[col + 1];
#pragma unroll
            for (int half = 0; half < 2; half++) {
                const int row = row0 + mt * 16 + half * 8;
                float v0 = acc[mt][nt][half * 2 + 0] + b0;
                float v1 = acc[mt][nt][half * 2 + 1] + b1;
                if (DUAL) {
                    if (second) { v0 = silu_f(v0); v1 = silu_f(v1); }
                } else {
                    if (MODE == 1) { v0 = silu_f(v0); v1 = silu_f(v1); }
                    else if (MODE == 2) { v0 = softplus_f(v0); v1 = softplus_f(v1); }
                }
                float2 w; w.x = v0; w.y = v1;
                *(float2*)(C + (size_t)row * DD + col) = w;
            }
        }
    }
}

template<int MODE>
__global__ __launch_bounds__(512, 1)
void gemm_mma(const Bb16* __restrict__ Ah, const Bb16* __restrict__ Al,
              const Bb16* __restrict__ Bh, const Bb16* __restrict__ Bl,
              const float* __restrict__ bias, float* __restrict__ C)
{
    gemm_body<MODE, 0>(Ah, Al, Bh, Bl, nullptr, nullptr, bias, nullptr, C, nullptr);
}

__global__ __launch_bounds__(512, 1)
void gemm_dual(const Bb16* __restrict__ Ah, const Bb16* __restrict__ Al,
               const Bb16* __restrict__ B0h, const Bb16* __restrict__ B0l,
               const Bb16* __restrict__ B1h, const Bb16* __restrict__ B1l,
               const float* __restrict__ bias0, const float* __restrict__ bias1,
               float* __restrict__ C0, float* __restrict__ C1)
{
    gemm_body<0, 1>(Ah, Al, B0h, B0l, B1h, B1l, bias0, bias1, C0, C1);
}

// ---------------- fused prep: weights transpose+split (z<4) + u split (z=4..7) ----------------
__global__ __launch_bounds__(256)
void prep_kernel(const float* __restrict__ W0, const float* __restrict__ W1,
                 const float* __restrict__ W2, const float* __restrict__ W3,
                 const float* __restrict__ u,
                 Bb16* __restrict__ T0h, Bb16* __restrict__ T0l,
                 Bb16* __restrict__ T1h, Bb16* __restrict__ T1l,
                 Bb16* __restrict__ T2h, Bb16* __restrict__ T2l,
                 Bb16* __restrict__ T3h, Bb16* __restrict__ T3l,
                 Bb16* __restrict__ uh, Bb16* __restrict__ ul)
{
    const int wi = blockIdx.z;
    if (wi < 4) {
        __shared__ float s[32][33];
        const float* W = (wi == 0) ? W0 : (wi == 1) ? W1 : (wi == 2) ? W2 : W3;
        Bb16* Th = (wi == 0) ? T0h : (wi == 1) ? T1h : (wi == 2) ? T2h : T3h;
        Bb16* Tl = (wi == 0) ? T0l : (wi == 1) ? T1l : (wi == 2) ? T2l : T3l;
        const int bx = blockIdx.x * 32, by = blockIdx.y * 32;
        const int tx = threadIdx.x & 31, ty = threadIdx.x >> 5;  // 32x8
#pragma unroll
        for (int j = ty; j < 32; j += 8)
            s[j][tx] = W[(size_t)(by + j) * DD + bx + tx];
        __syncthreads();
#pragma unroll
        for (int j = ty; j < 32; j += 8) {
            float v = s[tx][j];
            Bb16 h, l;
            split2(v, h, l);
            Th[(size_t)(bx + j) * DD + by + tx] = h;
            Tl[(size_t)(bx + j) * DD + by + tx] = l;
        }
    } else {
        // u split: 4 z-slices x 1024 xy-blocks x 256 thr x 1 float4 = 4M elems
        const int zi = wi - 4;
        const int blk = blockIdx.y * 32 + blockIdx.x;      // 0..1023
        const int i = (zi * 1024 + blk) * 256 + threadIdx.x;  // float4 index
        float4 v = ((const float4*)u)[i];
        Bb16 h0, l0, h1, l1, h2, l2, h3, l3;
        split2(v.x, h0, l0); split2(v.y, h1, l1); split2(v.z, h2, l2); split2(v.w, h3, l3);
        __nv_bfloat162 hh0; hh0.x = h0; hh0.y = h1;
        __nv_bfloat162 hh1; hh1.x = h2; hh1.y = h3;
        __nv_bfloat162 ll0; ll0.x = l0; ll0.y = l1;
        __nv_bfloat162 ll1; ll1.x = l2; ll1.y = l3;
        ((__nv_bfloat162*)uh)[i * 2]     = hh0;
        ((__nv_bfloat162*)uh)[i * 2 + 1] = hh1;
        ((__nv_bfloat162*)ul)[i * 2]     = ll0;
        ((__nv_bfloat162*)ul)[i * 2 + 1] = ll1;
    }
}

// ---------------- depthwise conv3 + silu (+ bf16 split out) ----------------
__global__ __launch_bounds__(256)
void conv_silu_kernel(const float* __restrict__ x1, const float* __restrict__ w,
                      const float* __restrict__ cb, float* __restrict__ x3,
                      Bb16* __restrict__ x3h, Bb16* __restrict__ x3l)
{
    const int total2 = BB * TT * DD / 2;
    for (int i2 = blockIdx.x * blockDim.x + threadIdx.x; i2 < total2; i2 += gridDim.x * blockDim.x) {
        int idx = i2 * 2;
        int d = idx & (DD - 1);
        int t = (idx / DD) & (TT - 1);
        float2 xc = *(const float2*)(x1 + idx);
        float c0 = xc.x * w[d * 3 + 1] + cb[d];
        float c1 = xc.y * w[(d + 1) * 3 + 1] + cb[d + 1];
        if (t > 0) {
            float2 xm = *(const float2*)(x1 + idx - DD);
            c0 = fmaf(xm.x, w[d * 3], c0);
            c1 = fmaf(xm.y, w[(d + 1) * 3], c1);
        }
        if (t < TT - 1) {
            float2 xp = *(const float2*)(x1 + idx + DD);
            c0 = fmaf(xp.x, w[d * 3 + 2], c0);
            c1 = fmaf(xp.y, w[(d + 1) * 3 + 2], c1);
        }
        float2 r; r.x = silu_f(c0); r.y = silu_f(c1);
        *(float2*)(x3 + idx) = r;
        Bb16 h0, l0, h1, l1;
        split2(r.x, h0, l0); split2(r.y, h1, l1);
        __nv_bfloat162 hh; hh.x = h0; hh.y = h1;
        __nv_bfloat162 ll; ll.x = l0; ll.y = l1;
        *(__nv_bfloat162*)(x3h + idx) = hh;
        *(__nv_bfloat162*)(x3l + idx) = ll;
    }
}

// ---------------- B/C projections ----------------
__global__ __launch_bounds__(256)
void proj_bc_kernel(const float* __restrict__ X,
                    const float* __restrict__ Wb, const float* __restrict__ Wc,
                    const float* __restrict__ bb, const float* __restrict__ bc,
                    float* __restrict__ Bm, float* __restrict__ Cm)
{
    __shared__ float Xs[32][33];
    __shared__ float Ws[32][32];
    const int tid = threadIdx.x;
    const int row0 = blockIdx.x * 32;
    const int c = tid & 31;
    const int rq = tid >> 5;
    float acc[4] = {0.f, 0.f, 0.f, 0.f};
    const int lr = tid / 8;
    const int lc = (tid % 8) * 4;

    for (int k0 = 0; k0 < DD; k0 += 32) {
        float4 xv = *(const float4*)(X + (size_t)(row0 + lr) * DD + k0 + lc);
        Xs[lr][lc + 0] = xv.x; Xs[lr][lc + 1] = xv.y;
        Xs[lr][lc + 2] = xv.z; Xs[lr][lc + 3] = xv.w;
#pragma unroll
        for (int q = 0; q < 4; q++) {
            int cc = lc + q;
            float wv = (cc < 16) ? Wb[(size_t)(k0 + lr) * 16 + cc]
                                 : Wc[(size_t)(k0 + lr) * 16 + cc - 16];
            Ws[lr][cc] = wv;
        }
        __syncthreads();
#pragma unroll
        for (int kk = 0; kk < 32; kk++) {
            float w = Ws[kk][c];
#pragma unroll
            for (int r = 0; r < 4; r++)
                acc[r] = fmaf(Xs[rq * 4 + r][kk], w, acc[r]);
        }
        __syncthreads();
    }
#pragma unroll
    for (int r = 0; r < 4; r++) {
        int row = row0 + rq * 4 + r;
        if (c < 16) Bm[(size_t)row * 16 + c]      = acc[r] + bb[c];
        else        Cm[(size_t)row * 16 + c - 16] = acc[r] + bc[c - 16];
    }
}

// ---------------- selective scan: 512 thr, SC=32, cp.async double-buffer ----------------
#define SC 32
__global__ __launch_bounds__(512)
void scan_kernel(const float* __restrict__ dt, const float* __restrict__ x,
                 const float* __restrict__ Bm, const float* __restrict__ Cm,
                 const float* __restrict__ A,  const float* __restrict__ z,
                 Bb16* __restrict__ yh, Bb16* __restrict__ yl)
{
    __shared__ float s_dt[2][SC][32], s_x[2][SC][32], s_z[2][SC][32];
    __shared__ float s_B[2][SC][16], s_C[2][SC][16];
    __shared__ float s_y[SC][32];

    const int blk = blockIdx.x;
    const int b = blk >> 5;
    const int d0 = (blk & 31) * 32;
    const int tid = threadIdx.x;
    const int n = tid & 15;
    const int dl = tid >> 4;
    const int d = d0 + dl;

    const float a = A[(size_t)d * NN + n];
    float h = 0.f;

    const size_t base = (size_t)b * TT * DD;

    const int larr = tid >> 7;
    const int lrw  = (tid & 127) >> 2;
    const int lcc  = tid & 3;
    const int t2   = tid - 384;
    const int barr = t2 >> 6;
    const int brw  = (t2 & 63) >> 1;
    const int bcc  = (t2 & 1) * 2;

    auto load_chunk = [&](int buf, int t0) {
        if (larr < 3) {
            const float* src = (larr == 0) ? dt : (larr == 1) ? x : z;
            float* sdst = (larr == 0) ? &s_dt[buf][lrw][0] :
                          (larr == 1) ? &s_x[buf][lrw][0] : &s_z[buf][lrw][0];
            const float* gsrc = src + base + (size_t)(t0 + lrw) * DD + d0;
            cpa16(smem_to_u32(sdst + lcc * 4),       gsrc + lcc * 4);
            cpa16(smem_to_u32(sdst + (lcc + 4) * 4), gsrc + (lcc + 4) * 4);
        } else {
            const float* src = barr ? Cm : Bm;
            float* sdst = barr ? &s_C[buf][brw][0] : &s_B[buf][brw][0];
            const float* gsrc = src + ((size_t)(b * TT) + t0 + brw) * NN;
            cpa16(smem_to_u32(sdst + bcc * 4),       gsrc + bcc * 4);
            cpa16(smem_to_u32(sdst + (bcc + 1) * 4), gsrc + (bcc + 1) * 4);
        }
        cp_commit();
    };

    load_chunk(0, 0);
    load_chunk(1, SC);

    const int yi = tid >> 5;
    const int yd = tid & 31;

    for (int c = 0; c < TT / SC; c++) {
        const int buf = c & 1;
        const int t0 = c * SC;
        if (c < TT / SC - 1) cp_wait<1>(); else cp_wait<0>();
        __syncthreads();

#pragma unroll 16
        for (int i = 0; i < SC; i++) {
            float dtv = s_dt[buf][i][dl];
            float xv  = s_x[buf][i][dl];
            float Bv  = s_B[buf][i][n];
            float Cv  = s_C[buf][i][n];
            float da  = __expf(dtv * a);
            h = fmaf(da, h, dtv * Bv * xv);
            float p = h * Cv;
            p += __shfl_xor_sync(0xffffffffu, p, 1);
            p += __shfl_xor_sync(0xffffffffu, p, 2);
            p += __shfl_xor_sync(0xffffffffu, p, 4);
            p += __shfl_xor_sync(0xffffffffu, p, 8);
            if (n == 0) s_y[i][dl] = p * s_z[buf][i][dl];
        }
        __syncthreads();

#pragma unroll
        for (int r = 0; r < 2; r++) {
            const int row = yi + r * 16;
            float v = s_y[row][yd];
            Bb16 hh, ll;
            split2(v, hh, ll);
            size_t off = base + (size_t)(t0 + row) * DD + d0 + yd;
            yh[off] = hh;
            yl[off] = ll;
        }

        if (c + 2 < TT / SC) load_chunk(buf, t0 + 2 * SC);
        else cp_commit();
        __syncthreads();
    }
}

// ---------------- launch ----------------
extern "C" void kernel_launch(void* const* d_in, const int* in_sizes, int n_in,
                              void* d_out, int out_size)
{
    const float* u    = (const float*)d_in[0];
    const float* Win  = (const float*)d_in[1];
    const float* b_in = (const float*)d_in[2];
    const float* Wg   = (const float*)d_in[3];
    const float* bg   = (const float*)d_in[4];
    const float* Wout = (const float*)d_in[5];
    const float* bout = (const float*)d_in[6];
    const float* convw= (const float*)d_in[7];
    const float* convb= (const float*)d_in[8];
    const float* A    = (const float*)d_in[9];
    const float* Wb   = (const float*)d_in[10];
    const float* bb   = (const float*)d_in[11];
    const float* Wc   = (const float*)d_in[12];
    const float* bc   = (const float*)d_in[13];
    const float* Wdt  = (const float*)d_in[14];
    const float* bdt  = (const float*)d_in[15];
    float* out = (float*)d_out;

    float *x1, *zb, *x3, *dtb, *Bmb, *Cmb;
    cudaGetSymbolAddress((void**)&x1,  g_x1);
    cudaGetSymbolAddress((void**)&zb,  g_z);
    cudaGetSymbolAddress((void**)&x3,  g_x3);
    cudaGetSymbolAddress((void**)&dtb, g_dt);
    cudaGetSymbolAddress((void**)&Bmb, g_Bm);
    cudaGetSymbolAddress((void**)&Cmb, g_Cm);

    Bb16 *uh, *ul, *x3h, *x3l, *yh, *yl;
    Bb16 *Wint_h, *Wint_l, *Wgt_h, *Wgt_l, *Wdtt_h, *Wdtt_l, *Wot_h, *Wot_l;
    cudaGetSymbolAddress((void**)&uh,  g_uh);   cudaGetSymbolAddress((void**)&ul,  g_ul);
    cudaGetSymbolAddress((void**)&x3h, g_x3h);  cudaGetSymbolAddress((void**)&x3l, g_x3l);
    cudaGetSymbolAddress((void**)&yh,  g_yh);   cudaGetSymbolAddress((void**)&yl,  g_yl);
    cudaGetSymbolAddress((void**)&Wint_h, g_Wint_h); cudaGetSymbolAddress((void**)&Wint_l, g_Wint_l);
    cudaGetSymbolAddress((void**)&Wgt_h,  g_Wgt_h);  cudaGetSymbolAddress((void**)&Wgt_l,  g_Wgt_l);
    cudaGetSymbolAddress((void**)&Wdtt_h, g_Wdtt_h); cudaGetSymbolAddress((void**)&Wdtt_l, g_Wdtt_l);
    cudaGetSymbolAddress((void**)&Wot_h,  g_Wot_h);  cudaGetSymbolAddress((void**)&Wot_l,  g_Wot_l);

    cudaFuncSetAttribute((const void*)gemm_mma<0>, cudaFuncAttributeMaxDynamicSharedMemorySize, GEMM_SMEM);
    cudaFuncSetAttribute((const void*)gemm_mma<2>, cudaFuncAttributeMaxDynamicSharedMemorySize, GEMM_SMEM);
    cudaFuncSetAttribute((const void*)gemm_dual,   cudaFuncAttributeMaxDynamicSharedMemorySize, GEMM_SMEM);

    static cudaStream_t s1 = nullptr;
    static cudaEvent_t evC = nullptr, evP = nullptr;
    if (!s1) {
        int prLo = 0, prHi = 0;
        cudaDeviceGetStreamPriorityRange(&prLo, &prHi);
        cudaStreamCreateWithPriority(&s1, cudaStreamNonBlocking, prLo);
        cudaEventCreateWithFlags(&evC, cudaEventDisableTiming);
        cudaEventCreateWithFlags(&evP, cudaEventDisableTiming);
    }
    cudaStream_t s0 = 0;

    dim3 ggd(16, MM / GBM);   // dual: (16, 16) = 256 CTAs
    dim3 gg (8,  MM / GBM);   // single: (8, 16) = 128 CTAs

    // single prep kernel: weight tsplit (z<4) + u split (z=4..7)
    prep_kernel<<<dim3(32, 32, 8), 256, 0, s0>>>(Win, Wg, Wdt, Wout, u,
        Wint_h, Wint_l, Wgt_h, Wgt_l, Wdtt_h, Wdtt_l, Wot_h, Wot_l, uh, ul);

    // merged in_proj + gate: 256 CTAs of 256x128 tiles
    gemm_dual<<<ggd, 512, GEMM_SMEM, s0>>>(uh, ul, Wint_h, Wint_l, Wgt_h, Wgt_l,
                                           b_in, bg, x1, zb);

    conv_silu_kernel<<<2048, 256, 0, s0>>>(x1, convw, convb, x3, x3h, x3l);
    cudaEventRecord(evC, s0);

    cudaStreamWaitEvent(s1, evC, 0);
    proj_bc_kernel<<<MM / 32, 256, 0, s1>>>(x3, Wb, Wc, bb, bc, Bmb, Cmb);
    cudaEventRecord(evP, s1);

    gemm_mma<2><<<gg, 512, GEMM_SMEM, s0>>>(x3h, x3l, Wdtt_h, Wdtt_l, bdt, dtb);

    cudaStreamWaitEvent(s0, evP, 0);
    scan_kernel<<<BB * (DD / 32), 512, 0, s0>>>(dtb, x3, Bmb, Cmb, A, zb, yh, yl);
    gemm_mma<0><<<gg, 512, GEMM_SMEM, s0>>>(yh, yl, Wot_h, Wot_l, bout, out);
}

// round 16
// speedup vs baseline: 1.1238x; 1.0573x over previous
#include <cuda_runtime.h>
#include <cuda_bf16.h>
#include <math.h>
#include <stdint.h>

#define BB 4
#define TT 1024
#define DD 1024
#define NN 16
#define MM (BB*TT)   // 4096

// GEMM tiling: 256x128 CTA tile, 512 threads, GBK=32
#define Bb16 __nv_bfloat16
#define GBM 256
#define GBN 128
#define GBK 32
#define ROWB 64
#define TILE_A (GBM*ROWB)       // 16384 per digit
#define TILE_Bt (GBN*ROWB)      // 8192 per digit
#define OFF_AH 0
#define OFF_AL (TILE_A)
#define OFF_BH (2*TILE_A)
#define OFF_BL (2*TILE_A + TILE_Bt)
#define STAGE_B (2*TILE_A + 2*TILE_Bt)  // 49152
#define NPIPE 3
#define GEMM_SMEM (NPIPE*STAGE_B)       // 147456
#define NSTAGE (DD/GBK)         // 32

// ---------------- scratch ----------------
__device__ __align__(256) float g_x1[MM*DD];
__device__ __align__(256) float g_z [MM*DD];
__device__ __align__(256) float g_x3[MM*DD];
__device__ __align__(256) float g_dt[MM*DD];
__device__ __align__(256) float g_Bm[MM*NN];
__device__ __align__(256) float g_Cm[MM*NN];

__device__ __align__(256) Bb16 g_uh[MM*DD],  g_ul[MM*DD];
__device__ __align__(256) Bb16 g_x3h[MM*DD], g_x3l[MM*DD];
__device__ __align__(256) Bb16 g_yh[MM*DD],  g_yl[MM*DD];
__device__ __align__(256) Bb16 g_Wint_h[DD*DD], g_Wint_l[DD*DD];
__device__ __align__(256) Bb16 g_Wgt_h [DD*DD], g_Wgt_l [DD*DD];
__device__ __align__(256) Bb16 g_Wdtt_h[DD*DD], g_Wdtt_l[DD*DD];
__device__ __align__(256) Bb16 g_Wot_h [DD*DD], g_Wot_l [DD*DD];
__device__ __align__(256) Bb16 g_Wbc_h[128*DD], g_Wbc_l[128*DD];  // zero-init; rows 0..31 = [Wb|Wc]^T

__device__ __forceinline__ float silu_f(float v) { return v / (1.f + __expf(-v)); }
__device__ __forceinline__ float softplus_f(float v) { return (v > 20.f) ? v : log1pf(__expf(v)); }

__device__ __forceinline__ uint32_t smem_to_u32(const void* p) {
    uint32_t a;
    asm("{ .reg .u64 t; cvta.to.shared.u64 t, %1; cvt.u32.u64 %0, t; }" : "=r"(a) : "l"(p));
    return a;
}
__device__ __forceinline__ void cpa16(uint32_t s, const void* g) {
    asm volatile("cp.async.cg.shared.global [%0], [%1], 16;\n" :: "r"(s), "l"(g));
}
__device__ __forceinline__ void cp_commit() { asm volatile("cp.async.commit_group;\n" ::: "memory"); }
template<int N> __device__ __forceinline__ void cp_wait() { asm volatile("cp.async.wait_group %0;\n" :: "n"(N) : "memory"); }

__device__ __forceinline__ void ldsm_x4(uint32_t* r, uint32_t addr) {
    asm volatile("ldmatrix.sync.aligned.m8n8.x4.shared.b16 {%0,%1,%2,%3}, [%4];"
        : "=r"(r[0]), "=r"(r[1]), "=r"(r[2]), "=r"(r[3]) : "r"(addr));
}
__device__ __forceinline__ void ldsm_x2(uint32_t* r, uint32_t addr) {
    asm volatile("ldmatrix.sync.aligned.m8n8.x2.shared.b16 {%0,%1}, [%2];"
        : "=r"(r[0]), "=r"(r[1]) : "r"(addr));
}
__device__ __forceinline__ void mma16816(float* c, const uint32_t* a, const uint32_t* b) {
    asm volatile("mma.sync.aligned.m16n8k16.row.col.f32.bf16.bf16.f32 "
        "{%0,%1,%2,%3}, {%4,%5,%6,%7}, {%8,%9}, {%0,%1,%2,%3};"
        : "+f"(c[0]), "+f"(c[1]), "+f"(c[2]), "+f"(c[3])
        : "r"(a[0]), "r"(a[1]), "r"(a[2]), "r"(a[3]), "r"(b[0]), "r"(b[1]));
}

__device__ __forceinline__ void split2(float v, Bb16& h, Bb16& l) {
    h = __float2bfloat16(v);
    l = __float2bfloat16(v - __bfloat162float(h));
}

// ---------------- shared GEMM body: one 256x128 tile ----------------
// DUAL=0: single (MODE act). DUAL=1: bnr<8 -> set0 no-act C0, bnr>=8 -> set1 silu C1.
// DUAL=2: bnr<8 -> set0 softplus C0 (dt); bnr==8 -> Wbc, epilogue scatters to Bm(C1)/Cm(C2).
template<int MODE, int DUAL>
__device__ __forceinline__ void gemm_body(
    const Bb16* __restrict__ Ah, const Bb16* __restrict__ Al,
    const Bb16* __restrict__ B0h, const Bb16* __restrict__ B0l,
    const Bb16* __restrict__ B1h, const Bb16* __restrict__ B1l,
    const float* __restrict__ bias0, const float* __restrict__ bias1,
    const float* __restrict__ bias2,
    float* __restrict__ C0, float* __restrict__ C1, float* __restrict__ C2)
{
    extern __shared__ char smem[];
    const uint32_t sb = smem_to_u32(smem);
    const int tid = threadIdx.x;
    const int lane = tid & 31;
    const int wid = tid >> 5;
    const int wm = wid & 3;
    const int wn = wid >> 2;
    const int bnr = blockIdx.x;
    const int bm = blockIdx.y;

    const bool second = (DUAL >= 1) && (bnr >= 8);
    const int bn = second ? ((DUAL == 2) ? 0 : bnr - 8) : bnr;
    const Bb16* Bh = second ? B1h : B0h;
    const Bb16* Bl = second ? B1l : B0l;

    float acc[4][4][4];
#pragma unroll
    for (int i = 0; i < 4; i++)
#pragma unroll
        for (int j = 0; j < 4; j++)
#pragma unroll
            for (int k = 0; k < 4; k++) acc[i][j][k] = 0.f;

    const int arow = tid >> 1;
    const int ach  = tid & 1;
    const int asw  = (arow >> 1) & 3;
    const uint32_t a_sc0 = (uint32_t)arow * ROWB + (uint32_t)((ach * 2 + 0) ^ asw) * 16;
    const uint32_t a_sc1 = (uint32_t)arow * ROWB + (uint32_t)((ach * 2 + 1) ^ asw) * 16;
    const Bb16* gAh = Ah + (size_t)(bm * GBM + arow) * DD + ach * 16;
    const Bb16* gAl = Al + (size_t)(bm * GBM + arow) * DD + ach * 16;

    const int brow = (tid & 255) >> 1;
    const int bch  = tid & 1;
    const int bsw  = (brow >> 1) & 3;
    const uint32_t b_sc0 = (uint32_t)brow * ROWB + (uint32_t)((bch * 2 + 0) ^ bsw) * 16;
    const uint32_t b_sc1 = (uint32_t)brow * ROWB + (uint32_t)((bch * 2 + 1) ^ bsw) * 16;
    const Bb16* gBh = Bh + (size_t)(bn * GBN + brow) * DD + bch * 16;
    const Bb16* gBl = Bl + (size_t)(bn * GBN + brow) * DD + bch * 16;
    const bool doB = (tid < 256);

    auto load_stage = [&](int buf, int s) {
        const uint32_t st = sb + (uint32_t)buf * STAGE_B;
        const size_t k0 = (size_t)s * GBK;
        cpa16(st + OFF_AH + a_sc0, gAh + k0);
        cpa16(st + OFF_AH + a_sc1, gAh + k0 + 8);
        cpa16(st + OFF_AL + a_sc0, gAl + k0);
        cpa16(st + OFF_AL + a_sc1, gAl + k0 + 8);
        if (doB) {
            cpa16(st + OFF_BH + b_sc0, gBh + k0);
            cpa16(st + OFF_BH + b_sc1, gBh + k0 + 8);
            cpa16(st + OFF_BL + b_sc0, gBl + k0);
            cpa16(st + OFF_BL + b_sc1, gBl + k0 + 8);
        }
        cp_commit();
    };

    load_stage(0, 0);
    load_stage(1, 1);

    const int rA = lane & 15, hiA = lane >> 4;
    const int swA = (rA >> 1) & 3;
    const uint32_t a_base = OFF_AH + (uint32_t)(wm * 64 + rA) * ROWB;
    const uint32_t acs0 = (uint32_t)((0 + hiA) ^ swA) * 16;
    const uint32_t acs1 = (uint32_t)((2 + hiA) ^ swA) * 16;

    const int rB = lane & 7, hiB = (lane >> 3) & 1;
    const int swB = (rB >> 1) & 3;
    const uint32_t b_base = OFF_BH + (uint32_t)(wn * 32 + rB) * ROWB;
    const uint32_t bcs0 = (uint32_t)((0 + hiB) ^ swB) * 16;
    const uint32_t bcs1 = (uint32_t)((2 + hiB) ^ swB) * 16;

    for (int s = 0; s < NSTAGE; s++) {
        const int buf = s - (s / NPIPE) * NPIPE;
        if (s < NSTAGE - 1) cp_wait<1>(); else cp_wait<0>();
        __syncthreads();

        const uint32_t st = sb + (uint32_t)buf * STAGE_B;
#pragma unroll
        for (int kc = 0; kc < 2; kc++) {
            const uint32_t ac = kc ? acs1 : acs0;
            const uint32_t bc = kc ? bcs1 : bcs0;
            uint32_t bhf[4][2], blf[4][2];
#pragma unroll
            for (int nt = 0; nt < 4; nt++) {
                uint32_t ad = st + b_base + (uint32_t)nt * (8 * ROWB) + bc;
                ldsm_x2(bhf[nt], ad);
                ldsm_x2(blf[nt], ad + TILE_Bt);
            }
#pragma unroll
            for (int mt = 0; mt < 4; mt++) {
                uint32_t ad = st + a_base + (uint32_t)mt * (16 * ROWB) + ac;
                uint32_t ahf[4], alf[4];
                ldsm_x4(ahf, ad);
                ldsm_x4(alf, ad + TILE_A);
#pragma unroll
                for (int nt = 0; nt < 4; nt++) mma16816(acc[mt][nt], ahf, bhf[nt]);
#pragma unroll
                for (int nt = 0; nt < 4; nt++) mma16816(acc[mt][nt], ahf, blf[nt]);
#pragma unroll
                for (int nt = 0; nt < 4; nt++) mma16816(acc[mt][nt], alf, bhf[nt]);
            }
        }

        if (s + 2 < NSTAGE) {
            int nb = s + 2;
            load_stage(nb - (nb / NPIPE) * NPIPE, nb);
        }
    }

    const int row0 = bm * GBM + wm * 64 + (lane >> 2);

    if (DUAL == 2 && second) {
        // bc tile: only wn==0 columns (0..31) are valid
        if (wn != 0) return;
        const int colb = (lane & 3) * 2;
#pragma unroll
        for (int mt = 0; mt < 4; mt++) {
#pragma unroll
            for (int nt = 0; nt < 4; nt++) {
                const int col = nt * 8 + colb;   // 0..30, even
                const bool isB = (col < 16);
                const int cc = isB ? col : col - 16;
                const float bi0 = isB ? bias1[cc] : bias2[cc];
                const float bi1 = isB ? bias1[cc + 1] : bias2[cc + 1];
                float* dst = isB ? C1 : C2;
#pragma unroll
                for (int half = 0; half < 2; half++) {
                    const int row = row0 + mt * 16 + half * 8;
                    float2 w;
                    w.x = acc[mt][nt][half * 2 + 0] + bi0;
                    w.y = acc[mt][nt][half * 2 + 1] + bi1;
                    *(float2*)(dst + (size_t)row * 16 + cc) = w;
                }
            }
        }
        return;
    }

    const float* bias = (DUAL == 1 && second) ? bias1 : bias0;
    float* C = (DUAL == 1 && second) ? C1 : C0;
    const int col0 = bn * GBN + wn * 32 + (lane & 3) * 2;
#pragma unroll
    for (int mt = 0; mt < 4; mt++) {
#pragma unroll
        for (int nt = 0; nt < 4; nt++) {
            const int col = col0 + nt * 8;
            float b0 = bias[col], b1 = bias[col + 1];
#pragma unroll
            for (int half = 0; half < 2; half++) {
                const int row = row0 + mt * 16 + half * 8;
                float v0 = acc[mt][nt][half * 2 + 0] + b0;
                float v1 = acc[mt][nt][half * 2 + 1] + b1;
                if (DUAL == 1) {
                    if (second) { v0 = silu_f(v0); v1 = silu_f(v1); }
                } else {
                    if (MODE == 1) { v0 = silu_f(v0); v1 = silu_f(v1); }
                    else if (MODE == 2) { v0 = softplus_f(v0); v1 = softplus_f(v1); }
                }
                float2 w; w.x = v0; w.y = v1;
                *(float2*)(C + (size_t)row * DD + col) = w;
            }
        }
    }
}

template<int MODE>
__global__ __launch_bounds__(512, 1)
void gemm_mma(const Bb16* __restrict__ Ah, const Bb16* __restrict__ Al,
              const Bb16* __restrict__ Bh, const Bb16* __restrict__ Bl,
              const float* __restrict__ bias, float* __restrict__ C)
{
    gemm_body<MODE, 0>(Ah, Al, Bh, Bl, nullptr, nullptr, bias, nullptr, nullptr,
                       C, nullptr, nullptr);
}

__global__ __launch_bounds__(512, 1)
void gemm_dual(const Bb16* __restrict__ Ah, const Bb16* __restrict__ Al,
               const Bb16* __restrict__ B0h, const Bb16* __restrict__ B0l,
               const Bb16* __restrict__ B1h, const Bb16* __restrict__ B1l,
               const float* __restrict__ bias0, const float* __restrict__ bias1,
               float* __restrict__ C0, float* __restrict__ C1)
{
    gemm_body<0, 1>(Ah, Al, B0h, B0l, B1h, B1l, bias0, bias1, nullptr, C0, C1, nullptr);
}

__global__ __launch_bounds__(512, 1)
void gemm_dtbc(const Bb16* __restrict__ Ah, const Bb16* __restrict__ Al,
               const Bb16* __restrict__ Bdth, const Bb16* __restrict__ Bdtl,
               const Bb16* __restrict__ Bbch, const Bb16* __restrict__ Bbcl,
               const float* __restrict__ bdt, const float* __restrict__ bb,
               const float* __restrict__ bc,
               float* __restrict__ dt, float* __restrict__ Bm, float* __restrict__ Cm)
{
    gemm_body<2, 2>(Ah, Al, Bdth, Bdtl, Bbch, Bbcl, bdt, bb, bc, dt, Bm, Cm);
}

// ---------------- prep A (critical): Win/Wg tsplit (z<2) + u split (z=2..5) ----------------
__global__ __launch_bounds__(256)
void prepA_kernel(const float* __restrict__ W0, const float* __restrict__ W1,
                  const float* __restrict__ u,
                  Bb16* __restrict__ T0h, Bb16* __restrict__ T0l,
                  Bb16* __restrict__ T1h, Bb16* __restrict__ T1l,
                  Bb16* __restrict__ uh, Bb16* __restrict__ ul)
{
    const int wi = blockIdx.z;
    if (wi < 2) {
        __shared__ float s[32][33];
        const float* W = (wi == 0) ? W0 : W1;
        Bb16* Th = (wi == 0) ? T0h : T1h;
        Bb16* Tl = (wi == 0) ? T0l : T1l;
        const int bx = blockIdx.x * 32, by = blockIdx.y * 32;
        const int tx = threadIdx.x & 31, ty = threadIdx.x >> 5;
#pragma unroll
        for (int j = ty; j < 32; j += 8)
            s[j][tx] = W[(size_t)(by + j) * DD + bx + tx];
        __syncthreads();
#pragma unroll
        for (int j = ty; j < 32; j += 8) {
            float v = s[tx][j];
            Bb16 h, l;
            split2(v, h, l);
            Th[(size_t)(bx + j) * DD + by + tx] = h;
            Tl[(size_t)(bx + j) * DD + by + tx] = l;
        }
    } else {
        const int zi = wi - 2;
        const int blk = blockIdx.y * 32 + blockIdx.x;
        const int i = (zi * 1024 + blk) * 256 + threadIdx.x;
        float4 v = ((const float4*)u)[i];
        Bb16 h0, l0, h1, l1, h2, l2, h3, l3;
        split2(v.x, h0, l0); split2(v.y, h1, l1); split2(v.z, h2, l2); split2(v.w, h3, l3);
        __nv_bfloat162 hh0; hh0.x = h0; hh0.y = h1;
        __nv_bfloat162 hh1; hh1.x = h2; hh1.y = h3;
        __nv_bfloat162 ll0; ll0.x = l0; ll0.y = l1;
        __nv_bfloat162 ll1; ll1.x = l2; ll1.y = l3;
        ((__nv_bfloat162*)uh)[i * 2]     = hh0;
        ((__nv_bfloat162*)uh)[i * 2 + 1] = hh1;
        ((__nv_bfloat162*)ul)[i * 2]     = ll0;
        ((__nv_bfloat162*)ul)[i * 2 + 1] = ll1;
    }
}

// ---------------- prep B (s1): Wdt/Wout tsplit (z<2) + Wbc build (z==2, blockIdx.y==0) ----------------
__global__ __launch_bounds__(256)
void prepB_kernel(const float* __restrict__ W2, const float* __restrict__ W3,
                  const float* __restrict__ Wb, const float* __restrict__ Wc,
                  Bb16* __restrict__ T2h, Bb16* __restrict__ T2l,
                  Bb16* __restrict__ T3h, Bb16* __restrict__ T3l,
                  Bb16* __restrict__ Wbch, Bb16* __restrict__ Wbcl)
{
    const int wi = blockIdx.z;
    if (wi < 2) {
        __shared__ float s[32][33];
        const float* W = (wi == 0) ? W2 : W3;
        Bb16* Th = (wi == 0) ? T2h : T3h;
        Bb16* Tl = (wi == 0) ? T2l : T3l;
        const int bx = blockIdx.x * 32, by = blockIdx.y * 32;
        const int tx = threadIdx.x & 31, ty = threadIdx.x >> 5;
#pragma unroll
        for (int j = ty; j < 32; j += 8)
            s[j][tx] = W[(size_t)(by + j) * DD + bx + tx];
        __syncthreads();
#pragma unroll
        for (int j = ty; j < 32; j += 8) {
            float v = s[tx][j];
            Bb16 h, l;
            split2(v, h, l);
            Th[(size_t)(bx + j) * DD + by + tx] = h;
            Tl[(size_t)(bx + j) * DD + by + tx] = l;
        }
    } else if (blockIdx.y == 0) {
        // Wbc rows 0..31: [Wb|Wc]^T. block x: k-range [bx*32, bx*32+32)
        const int k = blockIdx.x * 32 + (threadIdx.x >> 5);   // 8 k per block pass
        const int nn = threadIdx.x & 31;
#pragma unroll
        for (int kk = 0; kk < 4; kk++) {
            const int kq = k + kk * 8;
            float v = (nn < 16) ? Wb[(size_t)kq * 16 + nn] : Wc[(size_t)kq * 16 + nn - 16];
            Bb16 h, l;
            split2(v, h, l);
            Wbch[(size_t)nn * DD + kq] = h;
            Wbcl[(size_t)nn * DD + kq] = l;
        }
    }
}

// ---------------- depthwise conv3 + silu (+ bf16 split out) ----------------
__global__ __launch_bounds__(256)
void conv_silu_kernel(const float* __restrict__ x1, const float* __restrict__ w,
                      const float* __restrict__ cb, float* __restrict__ x3,
                      Bb16* __restrict__ x3h, Bb16* __restrict__ x3l)
{
    const int total2 = BB * TT * DD / 2;
    for (int i2 = blockIdx.x * blockDim.x + threadIdx.x; i2 < total2; i2 += gridDim.x * blockDim.x) {
        int idx = i2 * 2;
        int d = idx & (DD - 1);
        int t = (idx / DD) & (TT - 1);
        float2 xc = *(const float2*)(x1 + idx);
        float c0 = xc.x * w[d * 3 + 1] + cb[d];
        float c1 = xc.y * w[(d + 1) * 3 + 1] + cb[d + 1];
        if (t > 0) {
            float2 xm = *(const float2*)(x1 + idx - DD);
            c0 = fmaf(xm.x, w[d * 3], c0);
            c1 = fmaf(xm.y, w[(d + 1) * 3], c1);
        }
        if (t < TT - 1) {
            float2 xp = *(const float2*)(x1 + idx + DD);
            c0 = fmaf(xp.x, w[d * 3 + 2], c0);
            c1 = fmaf(xp.y, w[(d + 1) * 3 + 2], c1);
        }
        float2 r; r.x = silu_f(c0); r.y = silu_f(c1);
        *(float2*)(x3 + idx) = r;
        Bb16 h0, l0, h1, l1;
        split2(r.x, h0, l0); split2(r.y, h1, l1);
        __nv_bfloat162 hh; hh.x = h0; hh.y = h1;
        __nv_bfloat162 ll; ll.x = l0; ll.y = l1;
        *(__nv_bfloat162*)(x3h + idx) = hh;
        *(__nv_bfloat162*)(x3l + idx) = ll;
    }
}

// ---------------- selective scan: 512 thr, SC=32, cp.async double-buffer ----------------
#define SC 32
__global__ __launch_bounds__(512)
void scan_kernel(const float* __restrict__ dt, const float* __restrict__ x,
                 const float* __restrict__ Bm, const float* __restrict__ Cm,
                 const float* __restrict__ A,  const float* __restrict__ z,
                 Bb16* __restrict__ yh, Bb16* __restrict__ yl)
{
    __shared__ float s_dt[2][SC][32], s_x[2][SC][32], s_z[2][SC][32];
    __shared__ float s_B[2][SC][16], s_C[2][SC][16];
    __shared__ float s_y[SC][32];

    const int blk = blockIdx.x;
    const int b = blk >> 5;
    const int d0 = (blk & 31) * 32;
    const int tid = threadIdx.x;
    const int n = tid & 15;
    const int dl = tid >> 4;
    const int d = d0 + dl;

    const float a = A[(size_t)d * NN + n];
    float h = 0.f;

    const size_t base = (size_t)b * TT * DD;

    const int larr = tid >> 7;
    const int lrw  = (tid & 127) >> 2;
    const int lcc  = tid & 3;
    const int t2   = tid - 384;
    const int barr = t2 >> 6;
    const int brw  = (t2 & 63) >> 1;
    const int bcc  = (t2 & 1) * 2;

    auto load_chunk = [&](int buf, int t0) {
        if (larr < 3) {
            const float* src = (larr == 0) ? dt : (larr == 1) ? x : z;
            float* sdst = (larr == 0) ? &s_dt[buf][lrw][0] :
                          (larr == 1) ? &s_x[buf][lrw][0] : &s_z[buf][lrw][0];
            const float* gsrc = src + base + (size_t)(t0 + lrw) * DD + d0;
            cpa16(smem_to_u32(sdst + lcc * 4),       gsrc + lcc * 4);
            cpa16(smem_to_u32(sdst + (lcc + 4) * 4), gsrc + (lcc + 4) * 4);
        } else {
            const float* src = barr ? Cm : Bm;
            float* sdst = barr ? &s_C[buf][brw][0] : &s_B[buf][brw][0];
            const float* gsrc = src + ((size_t)(b * TT) + t0 + brw) * NN;
            cpa16(smem_to_u32(sdst + bcc * 4),       gsrc + bcc * 4);
            cpa16(smem_to_u32(sdst + (bcc + 1) * 4), gsrc + (bcc + 1) * 4);
        }
        cp_commit();
    };

    load_chunk(0, 0);
    load_chunk(1, SC);

    const int yi = tid >> 5;
    const int yd = tid & 31;

    for (int c = 0; c < TT / SC; c++) {
        const int buf = c & 1;
        const int t0 = c * SC;
        if (c < TT / SC - 1) cp_wait<1>(); else cp_wait<0>();
        __syncthreads();

#pragma unroll 16
        for (int i = 0; i < SC; i++) {
            float dtv = s_dt[buf][i][dl];
            float xv  = s_x[buf][i][dl];
            float Bv  = s_B[buf][i][n];
            float Cv  = s_C[buf][i][n];
            float da  = __expf(dtv * a);
            h = fmaf(da, h, dtv * Bv * xv);
            float p = h * Cv;
            p += __shfl_xor_sync(0xffffffffu, p, 1);
            p += __shfl_xor_sync(0xffffffffu, p, 2);
            p += __shfl_xor_sync(0xffffffffu, p, 4);
            p += __shfl_xor_sync(0xffffffffu, p, 8);
            if (n == 0) s_y[i][dl] = p * s_z[buf][i][dl];
        }
        __syncthreads();

#pragma unroll
        for (int r = 0; r < 2; r++) {
            const int row = yi + r * 16;
            float v = s_y[row][yd];
            Bb16 hh, ll;
            split2(v, hh, ll);
            size_t off = base + (size_t)(t0 + row) * DD + d0 + yd;
            yh[off] = hh;
            yl[off] = ll;
        }

        if (c + 2 < TT / SC) load_chunk(buf, t0 + 2 * SC);
        else cp_commit();
        __syncthreads();
    }
}

// ---------------- launch ----------------
extern "C" void kernel_launch(void* const* d_in, const int* in_sizes, int n_in,
                              void* d_out, int out_size)
{
    const float* u    = (const float*)d_in[0];
    const float* Win  = (const float*)d_in[1];
    const float* b_in = (const float*)d_in[2];
    const float* Wg   = (const float*)d_in[3];
    const float* bg   = (const float*)d_in[4];
    const float* Wout = (const float*)d_in[5];
    const float* bout = (const float*)d_in[6];
    const float* convw= (const float*)d_in[7];
    const float* convb= (const float*)d_in[8];
    const float* A    = (const float*)d_in[9];
    const float* Wb   = (const float*)d_in[10];
    const float* bb   = (const float*)d_in[11];
    const float* Wc   = (const float*)d_in[12];
    const float* bc   = (const float*)d_in[13];
    const float* Wdt  = (const float*)d_in[14];
    const float* bdt  = (const float*)d_in[15];
    float* out = (float*)d_out;

    float *x1, *zb, *x3, *dtb, *Bmb, *Cmb;
    cudaGetSymbolAddress((void**)&x1,  g_x1);
    cudaGetSymbolAddress((void**)&zb,  g_z);
    cudaGetSymbolAddress((void**)&x3,  g_x3);
    cudaGetSymbolAddress((void**)&dtb, g_dt);
    cudaGetSymbolAddress((void**)&Bmb, g_Bm);
    cudaGetSymbolAddress((void**)&Cmb, g_Cm);

    Bb16 *uh, *ul, *x3h, *x3l, *yh, *yl;
    Bb16 *Wint_h, *Wint_l, *Wgt_h, *Wgt_l, *Wdtt_h, *Wdtt_l, *Wot_h, *Wot_l, *Wbch, *Wbcl;
    cudaGetSymbolAddress((void**)&uh,  g_uh);   cudaGetSymbolAddress((void**)&ul,  g_ul);
    cudaGetSymbolAddress((void**)&x3h, g_x3h);  cudaGetSymbolAddress((void**)&x3l, g_x3l);
    cudaGetSymbolAddress((void**)&yh,  g_yh);   cudaGetSymbolAddress((void**)&yl,  g_yl);
    cudaGetSymbolAddress((void**)&Wint_h, g_Wint_h); cudaGetSymbolAddress((void**)&Wint_l, g_Wint_l);
    cudaGetSymbolAddress((void**)&Wgt_h,  g_Wgt_h);  cudaGetSymbolAddress((void**)&Wgt_l,  g_Wgt_l);
    cudaGetSymbolAddress((void**)&Wdtt_h, g_Wdtt_h); cudaGetSymbolAddress((void**)&Wdtt_l, g_Wdtt_l);
    cudaGetSymbolAddress((void**)&Wot_h,  g_Wot_h);  cudaGetSymbolAddress((void**)&Wot_l,  g_Wot_l);
    cudaGetSymbolAddress((void**)&Wbch, g_Wbc_h);    cudaGetSymbolAddress((void**)&Wbcl, g_Wbc_l);

    cudaFuncSetAttribute((const void*)gemm_mma<0>, cudaFuncAttributeMaxDynamicSharedMemorySize, GEMM_SMEM);
    cudaFuncSetAttribute((const void*)gemm_dual,   cudaFuncAttributeMaxDynamicSharedMemorySize, GEMM_SMEM);
    cudaFuncSetAttribute((const void*)gemm_dtbc,   cudaFuncAttributeMaxDynamicSharedMemorySize, GEMM_SMEM);

    static cudaStream_t s1 = nullptr;
    static cudaEvent_t ev0 = nullptr, evB = nullptr;
    if (!s1) {
        int prLo = 0, prHi = 0;
        cudaDeviceGetStreamPriorityRange(&prLo, &prHi);
        cudaStreamCreateWithPriority(&s1, cudaStreamNonBlocking, prLo);
        cudaEventCreateWithFlags(&ev0, cudaEventDisableTiming);
        cudaEventCreateWithFlags(&evB, cudaEventDisableTiming);
    }
    cudaStream_t s0 = 0;

    dim3 ggd(16, MM / GBM);   // dual: (16, 16) = 256 CTAs
    dim3 ggt(9,  MM / GBM);   // dt+bc: (9, 16) = 144 CTAs (one wave)
    dim3 gg (8,  MM / GBM);   // single: (8, 16) = 128 CTAs

    // fork s1; prepB (Wdt/Wout/Wbc) hides under prepA + dual
    cudaEventRecord(ev0, s0);
    cudaStreamWaitEvent(s1, ev0, 0);
    prepB_kernel<<<dim3(32, 32, 3), 256, 0, s1>>>(Wdt, Wout, Wb, Wc,
        Wdtt_h, Wdtt_l, Wot_h, Wot_l, Wbch, Wbcl);
    cudaEventRecord(evB, s1);

    // critical prep: Win/Wg + u
    prepA_kernel<<<dim3(32, 32, 6), 256, 0, s0>>>(Win, Wg, u,
        Wint_h, Wint_l, Wgt_h, Wgt_l, uh, ul);

    // merged in_proj + gate
    gemm_dual<<<ggd, 512, GEMM_SMEM, s0>>>(uh, ul, Wint_h, Wint_l, Wgt_h, Wgt_l,
                                           b_in, bg, x1, zb);

    conv_silu_kernel<<<2048, 256, 0, s0>>>(x1, convw, convb, x3, x3h, x3l);

    // dt + B/C projections in one GEMM (144 CTAs, one wave)
    cudaStreamWaitEvent(s0, evB, 0);
    gemm_dtbc<<<ggt, 512, GEMM_SMEM, s0>>>(x3h, x3l, Wdtt_h, Wdtt_l, Wbch, Wbcl,
                                           bdt, bb, bc, dtb, Bmb, Cmb);

    scan_kernel<<<BB * (DD / 32), 512, 0, s0>>>(dtb, x3, Bmb, Cmb, A, zb, yh, yl);
    gemm_mma<0><<<gg, 512, GEMM_SMEM, s0>>>(yh, yl, Wot_h, Wot_l, bout, out);
}

// round 17
// speedup vs baseline: 1.1791x; 1.0492x over previous
#include <cuda_runtime.h>
#include <cuda_bf16.h>
#include <math.h>
#include <stdint.h>

#define BB 4
#define TT 1024
#define DD 1024
#define NN 16
#define MM (BB*TT)   // 4096

// GEMM tiling: 256x128 CTA tile, 512 threads, GBK=32
#define Bb16 __nv_bfloat16
#define GBM 256
#define GBN 128
#define GBK 32
#define ROWB 64
#define TILE_A (GBM*ROWB)       // 16384 per digit
#define TILE_Bt (GBN*ROWB)      // 8192 per digit
#define OFF_AH 0
#define OFF_AL (TILE_A)
#define OFF_BH (2*TILE_A)
#define OFF_BL (2*TILE_A + TILE_Bt)
#define STAGE_B (2*TILE_A + 2*TILE_Bt)  // 49152
#define NPIPE 3
#define GEMM_SMEM (NPIPE*STAGE_B)       // 147456
#define NSTAGE (DD/GBK)         // 32

// ---------------- scratch ----------------
__device__ __align__(256) float g_x1[MM*DD];
__device__ __align__(256) float g_z [MM*DD];
__device__ __align__(256) float g_x3[MM*DD];
__device__ __align__(256) float g_dt[MM*DD];
__device__ __align__(256) float g_Bm[MM*NN];
__device__ __align__(256) float g_Cm[MM*NN];

__device__ __align__(256) Bb16 g_uh[MM*DD],  g_ul[MM*DD];
__device__ __align__(256) Bb16 g_x3h[MM*DD], g_x3l[MM*DD];
__device__ __align__(256) Bb16 g_yh[MM*DD],  g_yl[MM*DD];
__device__ __align__(256) Bb16 g_Wint_h[DD*DD], g_Wint_l[DD*DD];
__device__ __align__(256) Bb16 g_Wgt_h [DD*DD], g_Wgt_l [DD*DD];
__device__ __align__(256) Bb16 g_Wdtt_h[DD*DD], g_Wdtt_l[DD*DD];
__device__ __align__(256) Bb16 g_Wot_h [DD*DD], g_Wot_l [DD*DD];
__device__ __align__(256) Bb16 g_Wbc_h[128*DD], g_Wbc_l[128*DD];  // zero-init; rows 0..31 = [Wb|Wc]^T

__device__ __forceinline__ float silu_f(float v) { return v / (1.f + __expf(-v)); }
__device__ __forceinline__ float softplus_f(float v) { return (v > 20.f) ? v : log1pf(__expf(v)); }

__device__ __forceinline__ uint32_t smem_to_u32(const void* p) {
    uint32_t a;
    asm("{ .reg .u64 t; cvta.to.shared.u64 t, %1; cvt.u32.u64 %0, t; }" : "=r"(a) : "l"(p));
    return a;
}
__device__ __forceinline__ void cpa16(uint32_t s, const void* g) {
    asm volatile("cp.async.cg.shared.global [%0], [%1], 16;\n" :: "r"(s), "l"(g));
}
__device__ __forceinline__ void cp_commit() { asm volatile("cp.async.commit_group;\n" ::: "memory"); }
template<int N> __device__ __forceinline__ void cp_wait() { asm volatile("cp.async.wait_group %0;\n" :: "n"(N) : "memory"); }

__device__ __forceinline__ void ldsm_x4(uint32_t* r, uint32_t addr) {
    asm volatile("ldmatrix.sync.aligned.m8n8.x4.shared.b16 {%0,%1,%2,%3}, [%4];"
        : "=r"(r[0]), "=r"(r[1]), "=r"(r[2]), "=r"(r[3]) : "r"(addr));
}
__device__ __forceinline__ void ldsm_x2(uint32_t* r, uint32_t addr) {
    asm volatile("ldmatrix.sync.aligned.m8n8.x2.shared.b16 {%0,%1}, [%2];"
        : "=r"(r[0]), "=r"(r[1]) : "r"(addr));
}
__device__ __forceinline__ void mma16816(float* c, const uint32_t* a, const uint32_t* b) {
    asm volatile("mma.sync.aligned.m16n8k16.row.col.f32.bf16.bf16.f32 "
        "{%0,%1,%2,%3}, {%4,%5,%6,%7}, {%8,%9}, {%0,%1,%2,%3};"
        : "+f"(c[0]), "+f"(c[1]), "+f"(c[2]), "+f"(c[3])
        : "r"(a[0]), "r"(a[1]), "r"(a[2]), "r"(a[3]), "r"(b[0]), "r"(b[1]));
}

__device__ __forceinline__ void split2(float v, Bb16& h, Bb16& l) {
    h = __float2bfloat16(v);
    l = __float2bfloat16(v - __bfloat162float(h));
}

// ---------------- shared GEMM body: one 256x128 tile ----------------
// DUAL=0: single (MODE act). DUAL=2: bnr<8 -> softplus C0 (dt); bnr==8 -> Wbc -> Bm(C1)/Cm(C2).
template<int MODE, int DUAL>
__device__ __forceinline__ void gemm_body(
    const Bb16* __restrict__ Ah, const Bb16* __restrict__ Al,
    const Bb16* __restrict__ B0h, const Bb16* __restrict__ B0l,
    const Bb16* __restrict__ B1h, const Bb16* __restrict__ B1l,
    const float* __restrict__ bias0, const float* __restrict__ bias1,
    const float* __restrict__ bias2,
    float* __restrict__ C0, float* __restrict__ C1, float* __restrict__ C2)
{
    extern __shared__ char smem[];
    const uint32_t sb = smem_to_u32(smem);
    const int tid = threadIdx.x;
    const int lane = tid & 31;
    const int wid = tid >> 5;
    const int wm = wid & 3;
    const int wn = wid >> 2;
    const int bnr = blockIdx.x;
    const int bm = blockIdx.y;

    const bool second = (DUAL == 2) && (bnr >= 8);
    const int bn = second ? 0 : bnr;
    const Bb16* Bh = second ? B1h : B0h;
    const Bb16* Bl = second ? B1l : B0l;

    float acc[4][4][4];
#pragma unroll
    for (int i = 0; i < 4; i++)
#pragma unroll
        for (int j = 0; j < 4; j++)
#pragma unroll
            for (int k = 0; k < 4; k++) acc[i][j][k] = 0.f;

    const int arow = tid >> 1;
    const int ach  = tid & 1;
    const int asw  = (arow >> 1) & 3;
    const uint32_t a_sc0 = (uint32_t)arow * ROWB + (uint32_t)((ach * 2 + 0) ^ asw) * 16;
    const uint32_t a_sc1 = (uint32_t)arow * ROWB + (uint32_t)((ach * 2 + 1) ^ asw) * 16;
    const Bb16* gAh = Ah + (size_t)(bm * GBM + arow) * DD + ach * 16;
    const Bb16* gAl = Al + (size_t)(bm * GBM + arow) * DD + ach * 16;

    const int brow = (tid & 255) >> 1;
    const int bch  = tid & 1;
    const int bsw  = (brow >> 1) & 3;
    const uint32_t b_sc0 = (uint32_t)brow * ROWB + (uint32_t)((bch * 2 + 0) ^ bsw) * 16;
    const uint32_t b_sc1 = (uint32_t)brow * ROWB + (uint32_t)((bch * 2 + 1) ^ bsw) * 16;
    const Bb16* gBh = Bh + (size_t)(bn * GBN + brow) * DD + bch * 16;
    const Bb16* gBl = Bl + (size_t)(bn * GBN + brow) * DD + bch * 16;
    const bool doB = (tid < 256);

    auto load_stage = [&](int buf, int s) {
        const uint32_t st = sb + (uint32_t)buf * STAGE_B;
        const size_t k0 = (size_t)s * GBK;
        cpa16(st + OFF_AH + a_sc0, gAh + k0);
        cpa16(st + OFF_AH + a_sc1, gAh + k0 + 8);
        cpa16(st + OFF_AL + a_sc0, gAl + k0);
        cpa16(st + OFF_AL + a_sc1, gAl + k0 + 8);
        if (doB) {
            cpa16(st + OFF_BH + b_sc0, gBh + k0);
            cpa16(st + OFF_BH + b_sc1, gBh + k0 + 8);
            cpa16(st + OFF_BL + b_sc0, gBl + k0);
            cpa16(st + OFF_BL + b_sc1, gBl + k0 + 8);
        }
        cp_commit();
    };

    load_stage(0, 0);
    load_stage(1, 1);

    const int rA = lane & 15, hiA = lane >> 4;
    const int swA = (rA >> 1) & 3;
    const uint32_t a_base = OFF_AH + (uint32_t)(wm * 64 + rA) * ROWB;
    const uint32_t acs0 = (uint32_t)((0 + hiA) ^ swA) * 16;
    const uint32_t acs1 = (uint32_t)((2 + hiA) ^ swA) * 16;

    const int rB = lane & 7, hiB = (lane >> 3) & 1;
    const int swB = (rB >> 1) & 3;
    const uint32_t b_base = OFF_BH + (uint32_t)(wn * 32 + rB) * ROWB;
    const uint32_t bcs0 = (uint32_t)((0 + hiB) ^ swB) * 16;
    const uint32_t bcs1 = (uint32_t)((2 + hiB) ^ swB) * 16;

    for (int s = 0; s < NSTAGE; s++) {
        const int buf = s - (s / NPIPE) * NPIPE;
        if (s < NSTAGE - 1) cp_wait<1>(); else cp_wait<0>();
        __syncthreads();

        const uint32_t st = sb + (uint32_t)buf * STAGE_B;
#pragma unroll
        for (int kc = 0; kc < 2; kc++) {
            const uint32_t ac = kc ? acs1 : acs0;
            const uint32_t bc = kc ? bcs1 : bcs0;
            uint32_t bhf[4][2], blf[4][2];
#pragma unroll
            for (int nt = 0; nt < 4; nt++) {
                uint32_t ad = st + b_base + (uint32_t)nt * (8 * ROWB) + bc;
                ldsm_x2(bhf[nt], ad);
                ldsm_x2(blf[nt], ad + TILE_Bt);
            }
#pragma unroll
            for (int mt = 0; mt < 4; mt++) {
                uint32_t ad = st + a_base + (uint32_t)mt * (16 * ROWB) + ac;
                uint32_t ahf[4], alf[4];
                ldsm_x4(ahf, ad);
                ldsm_x4(alf, ad + TILE_A);
#pragma unroll
                for (int nt = 0; nt < 4; nt++) mma16816(acc[mt][nt], ahf, bhf[nt]);
#pragma unroll
                for (int nt = 0; nt < 4; nt++) mma16816(acc[mt][nt], ahf, blf[nt]);
#pragma unroll
                for (int nt = 0; nt < 4; nt++) mma16816(acc[mt][nt], alf, bhf[nt]);
            }
        }

        if (s + 2 < NSTAGE) {
            int nb = s + 2;
            load_stage(nb - (nb / NPIPE) * NPIPE, nb);
        }
    }

    const int row0 = bm * GBM + wm * 64 + (lane >> 2);

    if (DUAL == 2 && second) {
        if (wn != 0) return;
        const int colb = (lane & 3) * 2;
#pragma unroll
        for (int mt = 0; mt < 4; mt++) {
#pragma unroll
            for (int nt = 0; nt < 4; nt++) {
                const int col = nt * 8 + colb;
                const bool isB = (col < 16);
                const int cc = isB ? col : col - 16;
                const float bi0 = isB ? bias1[cc] : bias2[cc];
                const float bi1 = isB ? bias1[cc + 1] : bias2[cc + 1];
                float* dst = isB ? C1 : C2;
#pragma unroll
                for (int half = 0; half < 2; half++) {
                    const int row = row0 + mt * 16 + half * 8;
                    float2 w;
                    w.x = acc[mt][nt][half * 2 + 0] + bi0;
                    w.y = acc[mt][nt][half * 2 + 1] + bi1;
                    *(float2*)(dst + (size_t)row * 16 + cc) = w;
                }
            }
        }
        return;
    }

    const float* bias = bias0;
    float* C = C0;
    const int col0 = bn * GBN + wn * 32 + (lane & 3) * 2;
#pragma unroll
    for (int mt = 0; mt < 4; mt++) {
#pragma unroll
        for (int nt = 0; nt < 4; nt++) {
            const int col = col0 + nt * 8;
            float b0 = bias[col], b1 = bias[col + 1];
#pragma unroll
            for (int half = 0; half < 2; half++) {
                const int row = row0 + mt * 16 + half * 8;
                float v0 = acc[mt][nt][half * 2 + 0] + b0;
                float v1 = acc[mt][nt][half * 2 + 1] + b1;
                if (MODE == 1) { v0 = silu_f(v0); v1 = silu_f(v1); }
                else if (MODE == 2) { v0 = softplus_f(v0); v1 = softplus_f(v1); }
                float2 w; w.x = v0; w.y = v1;
                *(float2*)(C + (size_t)row * DD + col) = w;
            }
        }
    }
}

template<int MODE>
__global__ __launch_bounds__(512, 1)
void gemm_mma(const Bb16* __restrict__ Ah, const Bb16* __restrict__ Al,
              const Bb16* __restrict__ Bh, const Bb16* __restrict__ Bl,
              const float* __restrict__ bias, float* __restrict__ C)
{
    gemm_body<MODE, 0>(Ah, Al, Bh, Bl, nullptr, nullptr, bias, nullptr, nullptr,
                       C, nullptr, nullptr);
}

__global__ __launch_bounds__(512, 1)
void gemm_dtbc(const Bb16* __restrict__ Ah, const Bb16* __restrict__ Al,
               const Bb16* __restrict__ Bdth, const Bb16* __restrict__ Bdtl,
               const Bb16* __restrict__ Bbch, const Bb16* __restrict__ Bbcl,
               const float* __restrict__ bdt, const float* __restrict__ bb,
               const float* __restrict__ bc,
               float* __restrict__ dt, float* __restrict__ Bm, float* __restrict__ Cm)
{
    gemm_body<2, 2>(Ah, Al, Bdth, Bdtl, Bbch, Bbcl, bdt, bb, bc, dt, Bm, Cm);
}

// ---------------- prep A (critical): Win/Wg tsplit (z<2) + u split (z=2..5) ----------------
__global__ __launch_bounds__(256)
void prepA_kernel(const float* __restrict__ W0, const float* __restrict__ W1,
                  const float* __restrict__ u,
                  Bb16* __restrict__ T0h, Bb16* __restrict__ T0l,
                  Bb16* __restrict__ T1h, Bb16* __restrict__ T1l,
                  Bb16* __restrict__ uh, Bb16* __restrict__ ul)
{
    const int wi = blockIdx.z;
    if (wi < 2) {
        __shared__ float s[32][33];
        const float* W = (wi == 0) ? W0 : W1;
        Bb16* Th = (wi == 0) ? T0h : T1h;
        Bb16* Tl = (wi == 0) ? T0l : T1l;
        const int bx = blockIdx.x * 32, by = blockIdx.y * 32;
        const int tx = threadIdx.x & 31, ty = threadIdx.x >> 5;
#pragma unroll
        for (int j = ty; j < 32; j += 8)
            s[j][tx] = W[(size_t)(by + j) * DD + bx + tx];
        __syncthreads();
#pragma unroll
        for (int j = ty; j < 32; j += 8) {
            float v = s[tx][j];
            Bb16 h, l;
            split2(v, h, l);
            Th[(size_t)(bx + j) * DD + by + tx] = h;
            Tl[(size_t)(bx + j) * DD + by + tx] = l;
        }
    } else {
        const int zi = wi - 2;
        const int blk = blockIdx.y * 32 + blockIdx.x;
        const int i = (zi * 1024 + blk) * 256 + threadIdx.x;
        float4 v = ((const float4*)u)[i];
        Bb16 h0, l0, h1, l1, h2, l2, h3, l3;
        split2(v.x, h0, l0); split2(v.y, h1, l1); split2(v.z, h2, l2); split2(v.w, h3, l3);
        __nv_bfloat162 hh0; hh0.x = h0; hh0.y = h1;
        __nv_bfloat162 hh1; hh1.x = h2; hh1.y = h3;
        __nv_bfloat162 ll0; ll0.x = l0; ll0.y = l1;
        __nv_bfloat162 ll1; ll1.x = l2; ll1.y = l3;
        ((__nv_bfloat162*)uh)[i * 2]     = hh0;
        ((__nv_bfloat162*)uh)[i * 2 + 1] = hh1;
        ((__nv_bfloat162*)ul)[i * 2]     = ll0;
        ((__nv_bfloat162*)ul)[i * 2 + 1] = ll1;
    }
}

// ---------------- prep B (s1): Wdt/Wout tsplit (z<2) + Wbc build (z==2, y==0) ----------------
__global__ __launch_bounds__(256)
void prepB_kernel(const float* __restrict__ W2, const float* __restrict__ W3,
                  const float* __restrict__ Wb, const float* __restrict__ Wc,
                  Bb16* __restrict__ T2h, Bb16* __restrict__ T2l,
                  Bb16* __restrict__ T3h, Bb16* __restrict__ T3l,
                  Bb16* __restrict__ Wbch, Bb16* __restrict__ Wbcl)
{
    const int wi = blockIdx.z;
    if (wi < 2) {
        __shared__ float s[32][33];
        const float* W = (wi == 0) ? W2 : W3;
        Bb16* Th = (wi == 0) ? T2h : T3h;
        Bb16* Tl = (wi == 0) ? T2l : T3l;
        const int bx = blockIdx.x * 32, by = blockIdx.y * 32;
        const int tx = threadIdx.x & 31, ty = threadIdx.x >> 5;
#pragma unroll
        for (int j = ty; j < 32; j += 8)
            s[j][tx] = W[(size_t)(by + j) * DD + bx + tx];
        __syncthreads();
#pragma unroll
        for (int j = ty; j < 32; j += 8) {
            float v = s[tx][j];
            Bb16 h, l;
            split2(v, h, l);
            Th[(size_t)(bx + j) * DD + by + tx] = h;
            Tl[(size_t)(bx + j) * DD + by + tx] = l;
        }
    } else if (blockIdx.y == 0) {
        const int k = blockIdx.x * 32 + (threadIdx.x >> 5);
        const int nn = threadIdx.x & 31;
#pragma unroll
        for (int kk = 0; kk < 4; kk++) {
            const int kq = k + kk * 8;
            float v = (nn < 16) ? Wb[(size_t)kq * 16 + nn] : Wc[(size_t)kq * 16 + nn - 16];
            Bb16 h, l;
            split2(v, h, l);
            Wbch[(size_t)nn * DD + kq] = h;
            Wbcl[(size_t)nn * DD + kq] = l;
        }
    }
}

// ---------------- depthwise conv3 + silu (+ bf16 split out) ----------------
__global__ __launch_bounds__(256)
void conv_silu_kernel(const float* __restrict__ x1, const float* __restrict__ w,
                      const float* __restrict__ cb, float* __restrict__ x3,
                      Bb16* __restrict__ x3h, Bb16* __restrict__ x3l)
{
    const int total2 = BB * TT * DD / 2;
    for (int i2 = blockIdx.x * blockDim.x + threadIdx.x; i2 < total2; i2 += gridDim.x * blockDim.x) {
        int idx = i2 * 2;
        int d = idx & (DD - 1);
        int t = (idx / DD) & (TT - 1);
        float2 xc = *(const float2*)(x1 + idx);
        float c0 = xc.x * w[d * 3 + 1] + cb[d];
        float c1 = xc.y * w[(d + 1) * 3 + 1] + cb[d + 1];
        if (t > 0) {
            float2 xm = *(const float2*)(x1 + idx - DD);
            c0 = fmaf(xm.x, w[d * 3], c0);
            c1 = fmaf(xm.y, w[(d + 1) * 3], c1);
        }
        if (t < TT - 1) {
            float2 xp = *(const float2*)(x1 + idx + DD);
            c0 = fmaf(xp.x, w[d * 3 + 2], c0);
            c1 = fmaf(xp.y, w[(d + 1) * 3 + 2], c1);
        }
        float2 r; r.x = silu_f(c0); r.y = silu_f(c1);
        *(float2*)(x3 + idx) = r;
        Bb16 h0, l0, h1, l1;
        split2(r.x, h0, l0); split2(r.y, h1, l1);
        __nv_bfloat162 hh; hh.x = h0; hh.y = h1;
        __nv_bfloat162 ll; ll.x = l0; ll.y = l1;
        *(__nv_bfloat162*)(x3h + idx) = hh;
        *(__nv_bfloat162*)(x3l + idx) = ll;
    }
}

// ---------------- selective scan: 512 thr, SC=32, cp.async double-buffer ----------------
#define SC 32
__global__ __launch_bounds__(512)
void scan_kernel(const float* __restrict__ dt, const float* __restrict__ x,
                 const float* __restrict__ Bm, const float* __restrict__ Cm,
                 const float* __restrict__ A,  const float* __restrict__ z,
                 Bb16* __restrict__ yh, Bb16* __restrict__ yl)
{
    __shared__ float s_dt[2][SC][32], s_x[2][SC][32], s_z[2][SC][32];
    __shared__ float s_B[2][SC][16], s_C[2][SC][16];
    __shared__ float s_y[SC][32];

    const int blk = blockIdx.x;
    const int b = blk >> 5;
    const int d0 = (blk & 31) * 32;
    const int tid = threadIdx.x;
    const int n = tid & 15;
    const int dl = tid >> 4;
    const int d = d0 + dl;

    const float a = A[(size_t)d * NN + n];
    float h = 0.f;

    const size_t base = (size_t)b * TT * DD;

    const int larr = tid >> 7;
    const int lrw  = (tid & 127) >> 2;
    const int lcc  = tid & 3;
    const int t2   = tid - 384;
    const int barr = t2 >> 6;
    const int brw  = (t2 & 63) >> 1;
    const int bcc  = (t2 & 1) * 2;

    auto load_chunk = [&](int buf, int t0) {
        if (larr < 3) {
            const float* src = (larr == 0) ? dt : (larr == 1) ? x : z;
            float* sdst = (larr == 0) ? &s_dt[buf][lrw][0] :
                          (larr == 1) ? &s_x[buf][lrw][0] : &s_z[buf][lrw][0];
            const float* gsrc = src + base + (size_t)(t0 + lrw) * DD + d0;
            cpa16(smem_to_u32(sdst + lcc * 4),       gsrc + lcc * 4);
            cpa16(smem_to_u32(sdst + (lcc + 4) * 4), gsrc + (lcc + 4) * 4);
        } else {
            const float* src = barr ? Cm : Bm;
            float* sdst = barr ? &s_C[buf][brw][0] : &s_B[buf][brw][0];
            const float* gsrc = src + ((size_t)(b * TT) + t0 + brw) * NN;
            cpa16(smem_to_u32(sdst + bcc * 4),       gsrc + bcc * 4);
            cpa16(smem_to_u32(sdst + (bcc + 1) * 4), gsrc + (bcc + 1) * 4);
        }
        cp_commit();
    };

    load_chunk(0, 0);
    load_chunk(1, SC);

    const int yi = tid >> 5;
    const int yd = tid & 31;

    for (int c = 0; c < TT / SC; c++) {
        const int buf = c & 1;
        const int t0 = c * SC;
        if (c < TT / SC - 1) cp_wait<1>(); else cp_wait<0>();
        __syncthreads();

#pragma unroll 16
        for (int i = 0; i < SC; i++) {
            float dtv = s_dt[buf][i][dl];
            float xv  = s_x[buf][i][dl];
            float Bv  = s_B[buf][i][n];
            float Cv  = s_C[buf][i][n];
            float da  = __expf(dtv * a);
            h = fmaf(da, h, dtv * Bv * xv);
            float p = h * Cv;
            p += __shfl_xor_sync(0xffffffffu, p, 1);
            p += __shfl_xor_sync(0xffffffffu, p, 2);
            p += __shfl_xor_sync(0xffffffffu, p, 4);
            p += __shfl_xor_sync(0xffffffffu, p, 8);
            if (n == 0) s_y[i][dl] = p * s_z[buf][i][dl];
        }
        __syncthreads();

#pragma unroll
        for (int r = 0; r < 2; r++) {
            const int row = yi + r * 16;
            float v = s_y[row][yd];
            Bb16 hh, ll;
            split2(v, hh, ll);
            size_t off = base + (size_t)(t0 + row) * DD + d0 + yd;
            yh[off] = hh;
            yl[off] = ll;
        }

        if (c + 2 < TT / SC) load_chunk(buf, t0 + 2 * SC);
        else cp_commit();
        __syncthreads();
    }
}

// ---------------- launch ----------------
extern "C" void kernel_launch(void* const* d_in, const int* in_sizes, int n_in,
                              void* d_out, int out_size)
{
    const float* u    = (const float*)d_in[0];
    const float* Win  = (const float*)d_in[1];
    const float* b_in = (const float*)d_in[2];
    const float* Wg   = (const float*)d_in[3];
    const float* bg   = (const float*)d_in[4];
    const float* Wout = (const float*)d_in[5];
    const float* bout = (const float*)d_in[6];
    const float* convw= (const float*)d_in[7];
    const float* convb= (const float*)d_in[8];
    const float* A    = (const float*)d_in[9];
    const float* Wb   = (const float*)d_in[10];
    const float* bb   = (const float*)d_in[11];
    const float* Wc   = (const float*)d_in[12];
    const float* bc   = (const float*)d_in[13];
    const float* Wdt  = (const float*)d_in[14];
    const float* bdt  = (const float*)d_in[15];
    float* out = (float*)d_out;

    float *x1, *zb, *x3, *dtb, *Bmb, *Cmb;
    cudaGetSymbolAddress((void**)&x1,  g_x1);
    cudaGetSymbolAddress((void**)&zb,  g_z);
    cudaGetSymbolAddress((void**)&x3,  g_x3);
    cudaGetSymbolAddress((void**)&dtb, g_dt);
    cudaGetSymbolAddress((void**)&Bmb, g_Bm);
    cudaGetSymbolAddress((void**)&Cmb, g_Cm);

    Bb16 *uh, *ul, *x3h, *x3l, *yh, *yl;
    Bb16 *Wint_h, *Wint_l, *Wgt_h, *Wgt_l, *Wdtt_h, *Wdtt_l, *Wot_h, *Wot_l, *Wbch, *Wbcl;
    cudaGetSymbolAddress((void**)&uh,  g_uh);   cudaGetSymbolAddress((void**)&ul,  g_ul);
    cudaGetSymbolAddress((void**)&x3h, g_x3h);  cudaGetSymbolAddress((void**)&x3l, g_x3l);
    cudaGetSymbolAddress((void**)&yh,  g_yh);   cudaGetSymbolAddress((void**)&yl,  g_yl);
    cudaGetSymbolAddress((void**)&Wint_h, g_Wint_h); cudaGetSymbolAddress((void**)&Wint_l, g_Wint_l);
    cudaGetSymbolAddress((void**)&Wgt_h,  g_Wgt_h);  cudaGetSymbolAddress((void**)&Wgt_l,  g_Wgt_l);
    cudaGetSymbolAddress((void**)&Wdtt_h, g_Wdtt_h); cudaGetSymbolAddress((void**)&Wdtt_l, g_Wdtt_l);
    cudaGetSymbolAddress((void**)&Wot_h,  g_Wot_h);  cudaGetSymbolAddress((void**)&Wot_l,  g_Wot_l);
    cudaGetSymbolAddress((void**)&Wbch, g_Wbc_h);    cudaGetSymbolAddress((void**)&Wbcl, g_Wbc_l);

    cudaFuncSetAttribute((const void*)gemm_mma<0>, cudaFuncAttributeMaxDynamicSharedMemorySize, GEMM_SMEM);
    cudaFuncSetAttribute((const void*)gemm_mma<1>, cudaFuncAttributeMaxDynamicSharedMemorySize, GEMM_SMEM);
    cudaFuncSetAttribute((const void*)gemm_dtbc,   cudaFuncAttributeMaxDynamicSharedMemorySize, GEMM_SMEM);

    static cudaStream_t s1 = nullptr;
    static cudaEvent_t ev0 = nullptr, evB = nullptr, evA = nullptr, evG = nullptr;
    if (!s1) {
        int prLo = 0, prHi = 0;
        cudaDeviceGetStreamPriorityRange(&prLo, &prHi);
        cudaStreamCreateWithPriority(&s1, cudaStreamNonBlocking, prLo);
        cudaEventCreateWithFlags(&ev0, cudaEventDisableTiming);
        cudaEventCreateWithFlags(&evB, cudaEventDisableTiming);
        cudaEventCreateWithFlags(&evA, cudaEventDisableTiming);
        cudaEventCreateWithFlags(&evG, cudaEventDisableTiming);
    }
    cudaStream_t s0 = 0;

    dim3 ggt(9, MM / GBM);   // dt+bc: (9, 16) = 144 CTAs (one wave)
    dim3 gg (8, MM / GBM);   // single: (8, 16) = 128 CTAs

    // fork s1; prepB hides under prepA + in_proj
    cudaEventRecord(ev0, s0);
    cudaStreamWaitEvent(s1, ev0, 0);
    prepB_kernel<<<dim3(32, 32, 3), 256, 0, s1>>>(Wdt, Wout, Wb, Wc,
        Wdtt_h, Wdtt_l, Wot_h, Wot_l, Wbch, Wbcl);
    cudaEventRecord(evB, s1);

    // critical prep: Win/Wg + u
    prepA_kernel<<<dim3(32, 32, 6), 256, 0, s0>>>(Win, Wg, u,
        Wint_h, Wint_l, Wgt_h, Wgt_l, uh, ul);
    cudaEventRecord(evA, s0);

    // in_proj on critical path (128 CTAs = one wave)
    gemm_mma<0><<<gg, 512, GEMM_SMEM, s0>>>(uh, ul, Wint_h, Wint_l, b_in, x1);

    // gate on low-prio s1, fills idle slots during conv/dtbc/scan
    cudaStreamWaitEvent(s1, evA, 0);
    gemm_mma<1><<<gg, 512, GEMM_SMEM, s1>>>(uh, ul, Wgt_h, Wgt_l, bg, zb);
    cudaEventRecord(evG, s1);

    conv_silu_kernel<<<2048, 256, 0, s0>>>(x1, convw, convb, x3, x3h, x3l);

    cudaStreamWaitEvent(s0, evB, 0);
    gemm_dtbc<<<ggt, 512, GEMM_SMEM, s0>>>(x3h, x3l, Wdtt_h, Wdtt_l, Wbch, Wbcl,
                                           bdt, bb, bc, dtb, Bmb, Cmb);

    cudaStreamWaitEvent(s0, evG, 0);
    scan_kernel<<<BB * (DD / 32), 512, 0, s0>>>(dtb, x3, Bmb, Cmb, A, zb, yh, yl);
    gemm_mma<0><<<gg, 512, GEMM_SMEM, s0>>>(yh, yl, Wot_h, Wot_l, bout, out);
}